// round 13
// baseline (speedup 1.0000x reference)
#include <cuda_runtime.h>
#include <cuda_bf16.h>
#include <math.h>
#include <stdint.h>

#define TT 2048
#define HH 2048
#define NH 16
#define NKV 4
#define HD 128
#define NE 16
#define TOPK 4
#define NGRP 4
#define GSZ 4
#define TGRP 2
#define IM 1024
#define QKVD 3072
#define ATT_SCALE 0.08838834764831845f
#define EPSV 1e-6f

typedef __nv_bfloat16 bf16;

// ---------------- scratch (device globals; no allocations) ----------------
__device__ float g_res1[(size_t)TT * HH];
__device__ float g_qkv[(size_t)TT * QKVD];
__device__ float g_x2[(size_t)TT * HH];
__device__ bf16  g_xh[(size_t)TT * HH],  g_xl[(size_t)TT * HH];
__device__ bf16  g_x2h[(size_t)TT * HH], g_x2l[(size_t)TT * HH];
__device__ bf16  g_qh[(size_t)TT * (NH * HD)], g_ql[(size_t)TT * (NH * HD)];
__device__ bf16  g_attnh[(size_t)TT * HH], g_attnl[(size_t)TT * HH];
__device__ bf16  g_acth[(size_t)NE * TT * IM], g_actl[(size_t)NE * TT * IM];
__device__ bf16  g_kbh[(size_t)NKV * TT * HD], g_kbl[(size_t)NKV * TT * HD];
__device__ bf16  g_vth[(size_t)NKV * HD * TT], g_vtl[(size_t)NKV * HD * TT];
__device__ bf16  g_wqkvh[(size_t)HH * QKVD], g_wqkvl[(size_t)HH * QKVD];
__device__ bf16  g_woh[(size_t)HH * HH],     g_wol[(size_t)HH * HH];
__device__ bf16  g_wguh[(size_t)NE * HH * 2 * IM], g_wgul[(size_t)NE * HH * 2 * IM];
__device__ bf16  g_wdh[(size_t)NE * IM * HH],      g_wdl[(size_t)NE * IM * HH];
__device__ int   g_cnt[NE];
__device__ int   g_tok[NE * TT];
__device__ float g_wgt[NE * TT];
__device__ int   g_topk_id[TT * TOPK];
__device__ float g_topk_w[TT * TOPK];

// ---------------- helpers ----------------
__device__ __forceinline__ uint32_t smem_u32(const void* p) {
    uint32_t a;
    asm("{ .reg .u64 t; cvta.to.shared.u64 t, %1; cvt.u32.u64 %0, t; }" : "=r"(a) : "l"(p));
    return a;
}
__device__ __forceinline__ void split_bf(float v, bf16& h, bf16& l) {
    h = __float2bfloat16_rn(v);
    l = __float2bfloat16_rn(v - __bfloat162float(h));
}
__device__ __forceinline__ uint32_t pack2(bf16 a, bf16 b) {
    return (uint32_t)__bfloat16_as_ushort(a) | ((uint32_t)__bfloat16_as_ushort(b) << 16);
}
__device__ __forceinline__ void cpa(uint32_t d, const void* s, int sz) {
    asm volatile("cp.async.cg.shared.global [%0], [%1], 16, %2;" :: "r"(d), "l"(s), "r"(sz));
}
__device__ __forceinline__ void cpcommit() { asm volatile("cp.async.commit_group;" ::: "memory"); }
__device__ __forceinline__ void cpwaitN(int n) {
    if (n == 0)      asm volatile("cp.async.wait_group 0;" ::: "memory");
    else if (n == 1) asm volatile("cp.async.wait_group 1;" ::: "memory");
    else             asm volatile("cp.async.wait_group 2;" ::: "memory");
}
__device__ __forceinline__ void ldm4(uint32_t* r, uint32_t a) {
    asm volatile("ldmatrix.sync.aligned.m8n8.x4.shared.b16 {%0,%1,%2,%3}, [%4];"
                 : "=r"(r[0]), "=r"(r[1]), "=r"(r[2]), "=r"(r[3]) : "r"(a));
}
__device__ __forceinline__ void ldm4t(uint32_t* r, uint32_t a) {
    asm volatile("ldmatrix.sync.aligned.m8n8.x4.trans.shared.b16 {%0,%1,%2,%3}, [%4];"
                 : "=r"(r[0]), "=r"(r[1]), "=r"(r[2]), "=r"(r[3]) : "r"(a));
}
// non-volatile — lets ptxas schedule MMAs for ILP.
__device__ __forceinline__ void mma16816(float* c, const uint32_t* a, const uint32_t* b) {
    asm("mma.sync.aligned.m16n8k16.row.col.f32.bf16.bf16.f32 "
        "{%0,%1,%2,%3},{%4,%5,%6,%7},{%8,%9},{%0,%1,%2,%3};"
        : "+f"(c[0]), "+f"(c[1]), "+f"(c[2]), "+f"(c[3])
        : "r"(a[0]), "r"(a[1]), "r"(a[2]), "r"(a[3]), "r"(b[0]), "r"(b[1]));
}

// ---------------- mma.sync bf16x3 GEMM (B K-major, 3-stage, ILP-ordered MMAs) -----
// C[z][M][N] (+)= alpha * A[z] @ W[z] ; W stored [K][N] row-major, bf16 hi/lo.
// EPI: 0 fp32 store, 2 add X, 3 atomicAdd scatter, 5 silu(even)*odd -> bf16 hi/lo,
//      6 split-K (z = slice, batch 0), 7 split-K x2 + scatter (z = expert*2+slice).
#define BMT 128
#define BNT 128
#define BKT 32
#define AST 80u
#define BST 272u
#define A_SZ 10240u
#define B_SZ 8704u
#define STG2 (2u * A_SZ + 2u * B_SZ)   // 37888
#define NSTG 3
#define GSM (NSTG * 37888)             // 113664

template <bool GA, int EPI>
__global__ void __launch_bounds__(256, 2)
gemm_m(const bf16* __restrict__ Ah0, const bf16* __restrict__ Al0, int lda, long saz,
       const bf16* __restrict__ Bh0, const bf16* __restrict__ Bl0, int ldb, long sbz, int bdiv,
       float* __restrict__ C0, bf16* __restrict__ Oh0, bf16* __restrict__ Ol0, int ldc, long scz,
       int M0, int N, int K,
       const int* __restrict__ Mptr, const int* __restrict__ gidx0, int sgz,
       const float* __restrict__ X0, long sxz, float alpha) {
    int z = blockIdx.z;
    int zb = z, ksl = 0, kns = 1;
    if (EPI == 6) { zb = 0; ksl = z; kns = (int)gridDim.z; }
    if (EPI == 7) { zb = z >> 1; ksl = z & 1; kns = 2; }
    int M = Mptr ? Mptr[zb] : M0;
    int row0 = blockIdx.y * BMT, col0 = blockIdx.x * BNT;
    if (row0 >= M) return;

    extern __shared__ char smem[];
    uint32_t sb = smem_u32(smem);
    int tid = threadIdx.x, lane = tid & 31, wid = tid >> 5;
    const int m0w = (wid & 3) * 32, n0w = (wid >> 2) * 64;

    const int* gidxz = (GA || EPI == 3 || EPI == 7) ? gidx0 + (long)zb * sgz : nullptr;
    const float* X = (EPI == 2 || EPI == 3 || EPI == 7) ? X0 + (long)zb * sxz : nullptr;
    const bf16* Bh = Bh0 + (long)(zb / bdiv) * sbz + col0;
    const bf16* Bl = Bl0 + (long)(zb / bdiv) * sbz + col0;

    int nchTot = K / BKT;
    int c0 = (nchTot * ksl) / kns;
    int c1 = (nchTot * (ksl + 1)) / kns;

    int lrow = tid >> 1, lhalf = tid & 1;
    int ari = row0 + lrow;
    bool av = ari < M;
    long agrow = ari;
    if (GA) agrow = av ? (long)gidxz[ari] : 0;
    long arow2 = (GA ? agrow : (long)ari);
    const bf16* agh2 = Ah0 + (long)zb * saz + arow2 * (long)lda;
    const bf16* agl2 = Al0 + (long)zb * saz + arow2 * (long)lda;
    int asz = av ? 16 : 0;
    uint32_t dst_a = sb + lrow * AST + lhalf * 32;
    int brow = tid >> 3, bth = tid & 7;
    uint32_t dst_b = sb + 2 * A_SZ + brow * BST + bth * 32;

    auto cp_stage = [&](int buf, int k0) {
        uint32_t so = buf * STG2;
        long ko = k0 + lhalf * 16;
        cpa(dst_a + so,             agh2 + ko,     asz);
        cpa(dst_a + so + 16,        agh2 + ko + 8, asz);
        cpa(dst_a + so + A_SZ,      agl2 + ko,     asz);
        cpa(dst_a + so + A_SZ + 16, agl2 + ko + 8, asz);
        long bko = (long)(k0 + brow) * ldb + bth * 16;
        cpa(dst_b + so,             Bh + bko,     16);
        cpa(dst_b + so + 16,        Bh + bko + 8, 16);
        cpa(dst_b + so + B_SZ,      Bl + bko,     16);
        cpa(dst_b + so + B_SZ + 16, Bl + bko + 8, 16);
    };

    float acc[2][8][4];
#pragma unroll
    for (int i = 0; i < 2; i++)
#pragma unroll
        for (int j = 0; j < 8; j++)
#pragma unroll
            for (int q = 0; q < 4; q++) acc[i][j][q] = 0.f;

    uint32_t a_off = (uint32_t)(m0w + (lane & 15)) * AST + (uint32_t)(lane >> 4) * 16;
    uint32_t b_off = (uint32_t)((lane & 7) + ((lane >> 3) & 1) * 8) * BST
                   + (uint32_t)(lane >> 4) * 16;

    auto compute = [&](int buf) {
        uint32_t ab  = sb + buf * STG2;
        uint32_t alb = ab + A_SZ;
        uint32_t bhb = ab + 2 * A_SZ;
        uint32_t blb = bhb + B_SZ;
#pragma unroll
        for (int s = 0; s < 2; s++) {
            uint32_t ka = s * 32;
            uint32_t ah0[4], ah1[4], al0[4], al1[4];
            ldm4(ah0, ab + a_off + ka);
            ldm4(ah1, ab + a_off + 16 * AST + ka);
            ldm4(al0, alb + a_off + ka);
            ldm4(al1, alb + a_off + 16 * AST + ka);
            uint32_t bs = b_off + s * (16 * BST);
#pragma unroll
            for (int np = 0; np < 4; np++) {
                uint32_t bo = bs + (uint32_t)((n0w + np * 16) * 2);
                uint32_t bh[4], bl[4];
                ldm4t(bh, bhb + bo);
                ldm4t(bl, blb + bo);
                int ne = 2 * np, no = 2 * np + 1;
                mma16816(acc[0][ne], ah0, bh);     mma16816(acc[0][no], ah0, bh + 2);
                mma16816(acc[1][ne], ah1, bh);     mma16816(acc[1][no], ah1, bh + 2);
                mma16816(acc[0][ne], ah0, bl);     mma16816(acc[0][no], ah0, bl + 2);
                mma16816(acc[1][ne], ah1, bl);     mma16816(acc[1][no], ah1, bl + 2);
                mma16816(acc[0][ne], al0, bh);     mma16816(acc[0][no], al0, bh + 2);
                mma16816(acc[1][ne], al1, bh);     mma16816(acc[1][no], al1, bh + 2);
            }
        }
    };

    cp_stage(0, c0 * BKT); cpcommit();
    cp_stage(1, (c0 + 1) * BKT); cpcommit();
    int buf = 0;
    for (int c = c0; c < c1; c++) {
        cpwaitN(1);
        __syncthreads();
        compute(buf);
        int nb = buf + 1; if (nb == NSTG) nb = 0;
        int pb = buf + 2; if (pb >= NSTG) pb -= NSTG;
        if (c + 2 < c1) cp_stage(pb, (c + 2) * BKT);
        cpcommit();
        buf = nb;
    }

    // epilogue
    int lq = lane >> 2, lr = lane & 3;
#pragma unroll
    for (int mt = 0; mt < 2; mt++) {
        int r0 = row0 + m0w + mt * 16 + lq;
        int r1 = r0 + 8;
#pragma unroll
        for (int nt = 0; nt < 8; nt++) {
            long cc = (long)col0 + n0w + nt * 8 + 2 * lr;
            float v0 = acc[mt][nt][0] * alpha, v1 = acc[mt][nt][1] * alpha;
            float v2 = acc[mt][nt][2] * alpha, v3 = acc[mt][nt][3] * alpha;
            if (EPI == 6) {
                float* C = C0;
                if (r0 < M) {
                    atomicAdd(&C[(long)r0 * ldc + cc], v0);
                    atomicAdd(&C[(long)r0 * ldc + cc + 1], v1);
                }
                if (r1 < M) {
                    atomicAdd(&C[(long)r1 * ldc + cc], v2);
                    atomicAdd(&C[(long)r1 * ldc + cc + 1], v3);
                }
            } else if (EPI == 3 || EPI == 7) {
                float* C = C0 + (EPI == 3 ? (long)zb * scz : 0);
                if (r0 < M) {
                    long gr = gidxz[r0]; float w = X[r0];
                    atomicAdd(&C[gr * ldc + cc], w * v0);
                    atomicAdd(&C[gr * ldc + cc + 1], w * v1);
                }
                if (r1 < M) {
                    long gr = gidxz[r1]; float w = X[r1];
                    atomicAdd(&C[gr * ldc + cc], w * v2);
                    atomicAdd(&C[gr * ldc + cc + 1], w * v3);
                }
            } else if (EPI == 5) {
                bf16* oh = Oh0 + (long)zb * scz; bf16* ol = Ol0 + (long)zb * scz;
                long co = cc >> 1;
                if (r0 < M) {
                    float a = v0 / (1.f + expf(-v0)) * v1;
                    bf16 h, l; split_bf(a, h, l);
                    oh[(long)r0 * ldc + co] = h; ol[(long)r0 * ldc + co] = l;
                }
                if (r1 < M) {
                    float a = v2 / (1.f + expf(-v2)) * v3;
                    bf16 h, l; split_bf(a, h, l);
                    oh[(long)r1 * ldc + co] = h; ol[(long)r1 * ldc + co] = l;
                }
            } else if (EPI == 2) {
                float* C = C0 + (long)zb * scz;
                if (r0 < M) {
                    float2 xv = *(const float2*)&X[(long)r0 * ldc + cc];
                    *(float2*)&C[(long)r0 * ldc + cc] = make_float2(v0 + xv.x, v1 + xv.y);
                }
                if (r1 < M) {
                    float2 xv = *(const float2*)&X[(long)r1 * ldc + cc];
                    *(float2*)&C[(long)r1 * ldc + cc] = make_float2(v2 + xv.x, v3 + xv.y);
                }
            } else {
                float* C = C0 + (long)zb * scz;
                if (r0 < M) *(float2*)&C[(long)r0 * ldc + cc] = make_float2(v0, v1);
                if (r1 < M) *(float2*)&C[(long)r1 * ldc + cc] = make_float2(v2, v3);
            }
        }
    }
}

// ---------------- flash attention (bf16x3, online softmax) ----------------
#define FA_Q  0u
#define FA_QL 40960u
#define FA_K  81920u
#define FA_KL 122880u
#define FA_V  163840u
#define FA_VL 184320u
#define FA_SMEM 204800

__global__ void __launch_bounds__(256, 1) k_flash() {
    extern __shared__ char smem[];
    uint32_t sb = smem_u32(smem);
    int head = blockIdx.x;
    int qb = (int)gridDim.y - 1 - (int)blockIdx.y;
    int row0 = qb * 128;
    int kv = head >> 2;
    int tid = threadIdx.x, lane = tid & 31, w = tid >> 5;
    int lq = lane >> 2, lr = lane & 3;
    int lrow = tid >> 1, lhalf = tid & 1;

    const bf16* qgh = g_qh + (size_t)(row0 + lrow) * (NH * HD) + head * HD + lhalf * 16;
    const bf16* qgl = g_ql + (size_t)(row0 + lrow) * (NH * HD) + head * HD + lhalf * 16;
    const bf16* kgh = g_kbh + (size_t)kv * TT * HD + (size_t)lrow * HD + lhalf * 16;
    const bf16* kgl = g_kbl + (size_t)kv * TT * HD + (size_t)lrow * HD + lhalf * 16;
    const bf16* vgh = g_vth + (size_t)kv * HD * TT + (size_t)lrow * TT + lhalf * 16;
    const bf16* vgl = g_vtl + (size_t)kv * HD * TT + (size_t)lrow * TT + lhalf * 16;

#pragma unroll
    for (int c = 0; c < 4; c++) {
        uint32_t d = sb + FA_Q + (uint32_t)((c * 128 + lrow) * 80) + lhalf * 32;
        cpa(d, qgh + c * 32, 16); cpa(d + 16, qgh + c * 32 + 8, 16);
        uint32_t dl = d + (FA_QL - FA_Q);
        cpa(dl, qgl + c * 32, 16); cpa(dl + 16, qgl + c * 32 + 8, 16);
    }
    cpcommit();

    auto issueK = [&](int s0) {
#pragma unroll
        for (int c = 0; c < 4; c++) {
            uint32_t d = sb + FA_K + (uint32_t)((c * 128 + lrow) * 80) + lhalf * 32;
            const bf16* s = kgh + (size_t)s0 * HD + c * 32;
            cpa(d, s, 16); cpa(d + 16, s + 8, 16);
            uint32_t dl = d + (FA_KL - FA_K);
            const bf16* sl = kgl + (size_t)s0 * HD + c * 32;
            cpa(dl, sl, 16); cpa(dl + 16, sl + 8, 16);
        }
        cpcommit();
    };
    auto issueV = [&](int s0, int c) {
        uint32_t d = sb + FA_V + (uint32_t)(((c & 1) * 128 + lrow) * 80) + lhalf * 32;
        const bf16* s = vgh + s0 + c * 32;
        cpa(d, s, 16); cpa(d + 16, s + 8, 16);
        uint32_t dl = d + (FA_VL - FA_V);
        const bf16* sl = vgl + s0 + c * 32;
        cpa(dl, sl, 16); cpa(dl + 16, sl + 8, 16);
        cpcommit();
    };
    issueK(0);

    float O[16][4];
#pragma unroll
    for (int i = 0; i < 16; i++) { O[i][0] = O[i][1] = O[i][2] = O[i][3] = 0.f; }
    float m_lo = -1e30f, m_hi = -1e30f, l_lo = 0.f, l_hi = 0.f;
    int ntl = qb + 1;
    uint32_t a_off = (uint32_t)((w * 16 + (lane & 15)) * 80) + (uint32_t)(lane >> 4) * 16;
    uint32_t b_off = (uint32_t)((((lane >> 4) << 3) + (lane & 7)) * 80) + (uint32_t)((lane >> 3) & 1) * 16;

    for (int st = 0; st < ntl; st++) {
        int s0 = st * 128;
        __syncthreads();
        issueV(s0, 0); issueV(s0, 1);
        asm volatile("cp.async.wait_group 2;" ::: "memory");
        __syncthreads();

        float S[16][4];
#pragma unroll
        for (int i = 0; i < 16; i++) { S[i][0] = S[i][1] = S[i][2] = S[i][3] = 0.f; }
#pragma unroll
        for (int kc = 0; kc < 4; kc++)
#pragma unroll
        for (int ks = 0; ks < 2; ks++) {
            uint32_t qa = sb + (uint32_t)(kc * 128 * 80) + a_off + ks * 32;
            uint32_t ah[4], al[4];
            ldm4(ah, qa + FA_Q);
            ldm4(al, qa + FA_QL);
#pragma unroll
            for (int j = 0; j < 8; j++) {
                uint32_t kb = sb + FA_K + (uint32_t)((kc * 128 + 16 * j) * 80) + b_off + ks * 32;
                uint32_t bh[4], bl[4];
                ldm4(bh, kb); ldm4(bl, kb + (FA_KL - FA_K));
                mma16816(S[2 * j],     ah, bh);     mma16816(S[2 * j + 1], ah, bh + 2);
                mma16816(S[2 * j],     ah, bl);     mma16816(S[2 * j + 1], ah, bl + 2);
                mma16816(S[2 * j],     al, bh);     mma16816(S[2 * j + 1], al, bh + 2);
            }
        }

        bool dg = (st == qb);
        int rlo = row0 + w * 16 + lq, rhi = rlo + 8;
#pragma unroll
        for (int nt = 0; nt < 16; nt++) {
            int cbase = s0 + nt * 8 + 2 * lr;
#pragma unroll
            for (int q = 0; q < 4; q++) {
                float v = S[nt][q] * ATT_SCALE;
                int col = cbase + (q & 1);
                int rw = (q < 2) ? rlo : rhi;
                if (dg && col > rw) v = -1e30f;
                S[nt][q] = v;
            }
        }
        float mx0 = -1e30f, mx1 = -1e30f;
#pragma unroll
        for (int nt = 0; nt < 16; nt++) {
            mx0 = fmaxf(mx0, fmaxf(S[nt][0], S[nt][1]));
            mx1 = fmaxf(mx1, fmaxf(S[nt][2], S[nt][3]));
        }
        mx0 = fmaxf(mx0, __shfl_xor_sync(0xffffffffu, mx0, 1));
        mx0 = fmaxf(mx0, __shfl_xor_sync(0xffffffffu, mx0, 2));
        mx1 = fmaxf(mx1, __shfl_xor_sync(0xffffffffu, mx1, 1));
        mx1 = fmaxf(mx1, __shfl_xor_sync(0xffffffffu, mx1, 2));
        float mn0 = fmaxf(m_lo, mx0), mn1 = fmaxf(m_hi, mx1);
        float sc0 = expf(m_lo - mn0), sc1 = expf(m_hi - mn1);
        float rs0 = 0.f, rs1 = 0.f;
#pragma unroll
        for (int nt = 0; nt < 16; nt++) {
            S[nt][0] = expf(S[nt][0] - mn0); S[nt][1] = expf(S[nt][1] - mn0);
            S[nt][2] = expf(S[nt][2] - mn1); S[nt][3] = expf(S[nt][3] - mn1);
            rs0 += S[nt][0] + S[nt][1];
            rs1 += S[nt][2] + S[nt][3];
        }
        rs0 += __shfl_xor_sync(0xffffffffu, rs0, 1); rs0 += __shfl_xor_sync(0xffffffffu, rs0, 2);
        rs1 += __shfl_xor_sync(0xffffffffu, rs1, 1); rs1 += __shfl_xor_sync(0xffffffffu, rs1, 2);
        l_lo = l_lo * sc0 + rs0; l_hi = l_hi * sc1 + rs1;
        m_lo = mn0; m_hi = mn1;
#pragma unroll
        for (int nt = 0; nt < 16; nt++) {
            O[nt][0] *= sc0; O[nt][1] *= sc0; O[nt][2] *= sc1; O[nt][3] *= sc1;
        }

        __syncthreads();
        bool haveK = (st + 1 < ntl);
        if (haveK) issueK(s0 + 128);

#pragma unroll 1
        for (int c = 0; c < 4; c++) {
            int pend = haveK ? (c <= 1 ? 2 : (c == 2 ? 1 : 0)) : (c < 3 ? 1 : 0);
            cpwaitN(pend);
            __syncthreads();
#pragma unroll
            for (int ks = 0; ks < 2; ks++) {
                int t0 = 2 * (2 * c + ks), t1 = t0 + 1;
                uint32_t pah[4], pal[4];
                bf16 h0, l0, h1, l1;
                split_bf(S[t0][0], h0, l0); split_bf(S[t0][1], h1, l1);
                pah[0] = pack2(h0, h1); pal[0] = pack2(l0, l1);
                split_bf(S[t0][2], h0, l0); split_bf(S[t0][3], h1, l1);
                pah[1] = pack2(h0, h1); pal[1] = pack2(l0, l1);
                split_bf(S[t1][0], h0, l0); split_bf(S[t1][1], h1, l1);
                pah[2] = pack2(h0, h1); pal[2] = pack2(l0, l1);
                split_bf(S[t1][2], h0, l0); split_bf(S[t1][3], h1, l1);
                pah[3] = pack2(h0, h1); pal[3] = pack2(l0, l1);
#pragma unroll
                for (int j = 0; j < 8; j++) {
                    uint32_t vb = sb + FA_V + (uint32_t)((((c & 1) * 128) + 16 * j) * 80) + b_off + ks * 32;
                    uint32_t vh[4], vl[4];
                    ldm4(vh, vb); ldm4(vl, vb + (FA_VL - FA_V));
                    mma16816(O[2 * j],     pah, vh);     mma16816(O[2 * j + 1], pah, vh + 2);
                    mma16816(O[2 * j],     pah, vl);     mma16816(O[2 * j + 1], pah, vl + 2);
                    mma16816(O[2 * j],     pal, vh);     mma16816(O[2 * j + 1], pal, vh + 2);
                }
            }
            __syncthreads();
            if (c + 2 < 4) issueV(s0, c + 2);
        }
    }

    float il0 = 1.f / l_lo, il1 = 1.f / l_hi;
    int rlo = row0 + w * 16 + lq, rhi = rlo + 8;
#pragma unroll
    for (int nt = 0; nt < 16; nt++) {
        long col = (long)head * HD + nt * 8 + 2 * lr;
        bf16 h0, l0, h1, l1;
        float v0 = O[nt][0] * il0, v1 = O[nt][1] * il0;
        split_bf(v0, h0, l0); split_bf(v1, h1, l1);
        *(uint32_t*)&g_attnh[(long)rlo * HH + col] = pack2(h0, h1);
        *(uint32_t*)&g_attnl[(long)rlo * HH + col] = pack2(l0, l1);
        float v2 = O[nt][2] * il1, v3 = O[nt][3] * il1;
        split_bf(v2, h0, l0); split_bf(v3, h1, l1);
        *(uint32_t*)&g_attnh[(long)rhi * HH + col] = pack2(h0, h1);
        *(uint32_t*)&g_attnl[(long)rhi * HH + col] = pack2(l0, l1);
    }
}

// ---------------- streaming convert fp32 -> bf16 hi/lo (16 elems/thread, MLP=4) ---
__global__ void k_conv(const float* __restrict__ in, bf16* __restrict__ oh,
                       bf16* __restrict__ ol, long n) {
    long i = ((long)blockIdx.x * 256 + threadIdx.x) * 16;
    if (i >= n) return;
    float4 a0 = *(const float4*)(in + i);
    float4 a1 = *(const float4*)(in + i + 4);
    float4 a2 = *(const float4*)(in + i + 8);
    float4 a3 = *(const float4*)(in + i + 12);
    bf16 h0, l0, h1, l1;
    uint32_t H[8], L[8];
    split_bf(a0.x, h0, l0); split_bf(a0.y, h1, l1); H[0] = pack2(h0, h1); L[0] = pack2(l0, l1);
    split_bf(a0.z, h0, l0); split_bf(a0.w, h1, l1); H[1] = pack2(h0, h1); L[1] = pack2(l0, l1);
    split_bf(a1.x, h0, l0); split_bf(a1.y, h1, l1); H[2] = pack2(h0, h1); L[2] = pack2(l0, l1);
    split_bf(a1.z, h0, l0); split_bf(a1.w, h1, l1); H[3] = pack2(h0, h1); L[3] = pack2(l0, l1);
    split_bf(a2.x, h0, l0); split_bf(a2.y, h1, l1); H[4] = pack2(h0, h1); L[4] = pack2(l0, l1);
    split_bf(a2.z, h0, l0); split_bf(a2.w, h1, l1); H[5] = pack2(h0, h1); L[5] = pack2(l0, l1);
    split_bf(a3.x, h0, l0); split_bf(a3.y, h1, l1); H[6] = pack2(h0, h1); L[6] = pack2(l0, l1);
    split_bf(a3.z, h0, l0); split_bf(a3.w, h1, l1); H[7] = pack2(h0, h1); L[7] = pack2(l0, l1);
    *(uint4*)(oh + i)     = make_uint4(H[0], H[1], H[2], H[3]);
    *(uint4*)(oh + i + 8) = make_uint4(H[4], H[5], H[6], H[7]);
    *(uint4*)(ol + i)     = make_uint4(L[0], L[1], L[2], L[3]);
    *(uint4*)(ol + i + 8) = make_uint4(L[4], L[5], L[6], L[7]);
}

// gate/up column interleave (16 gate + 16 up per thread, MLP=8)
__global__ void k_conv_gu(const float* __restrict__ in, bf16* __restrict__ oh,
                          bf16* __restrict__ ol) {
    long t = (long)blockIdx.x * 256 + threadIdx.x;
    long rows = (long)NE * HH;
    long perRow = IM / 16;
    if (t >= rows * perRow) return;
    long row = t / perRow;
    long c = (t % perRow) * 16;
    const float* base = in + row * (2 * IM);
    float4 g0 = *(const float4*)(base + c);
    float4 g1 = *(const float4*)(base + c + 4);
    float4 g2 = *(const float4*)(base + c + 8);
    float4 g3 = *(const float4*)(base + c + 12);
    float4 u0 = *(const float4*)(base + IM + c);
    float4 u1 = *(const float4*)(base + IM + c + 4);
    float4 u2 = *(const float4*)(base + IM + c + 8);
    float4 u3 = *(const float4*)(base + IM + c + 12);
    bf16 hg, lg, hu, lu;
    uint32_t H[16], L[16];
    const float gv[16] = {g0.x, g0.y, g0.z, g0.w, g1.x, g1.y, g1.z, g1.w,
                          g2.x, g2.y, g2.z, g2.w, g3.x, g3.y, g3.z, g3.w};
    const float uv[16] = {u0.x, u0.y, u0.z, u0.w, u1.x, u1.y, u1.z, u1.w,
                          u2.x, u2.y, u2.z, u2.w, u3.x, u3.y, u3.z, u3.w};
#pragma unroll
    for (int j = 0; j < 16; j++) {
        split_bf(gv[j], hg, lg); split_bf(uv[j], hu, lu);
        H[j] = pack2(hg, hu); L[j] = pack2(lg, lu);
    }
    bf16* po = oh + row * (2 * IM) + 2 * c;
    bf16* pl = ol + row * (2 * IM) + 2 * c;
    *(uint4*)po        = make_uint4(H[0],  H[1],  H[2],  H[3]);
    *(uint4*)(po + 8)  = make_uint4(H[4],  H[5],  H[6],  H[7]);
    *(uint4*)(po + 16) = make_uint4(H[8],  H[9],  H[10], H[11]);
    *(uint4*)(po + 24) = make_uint4(H[12], H[13], H[14], H[15]);
    *(uint4*)pl        = make_uint4(L[0],  L[1],  L[2],  L[3]);
    *(uint4*)(pl + 8)  = make_uint4(L[4],  L[5],  L[6],  L[7]);
    *(uint4*)(pl + 16) = make_uint4(L[8],  L[9],  L[10], L[11]);
    *(uint4*)(pl + 24) = make_uint4(L[12], L[13], L[14], L[15]);
}

// ---------------- transpose + convert (V only) ----------------
__global__ void k_tconv(const float* __restrict__ in, long ldin, long sbin,
                        bf16* __restrict__ oh, bf16* __restrict__ ol, long ldo, long sbo,
                        int R, int C) {
    __shared__ float t[32][33];
    int z = blockIdx.z;
    const float* I = in + (long)z * sbin;
    int c0 = blockIdx.x * 32, r0 = blockIdx.y * 32;
#pragma unroll
    for (int i = 0; i < 4; i++) {
        int r = r0 + threadIdx.y + i * 8, c = c0 + threadIdx.x;
        t[threadIdx.y + i * 8][threadIdx.x] = (r < R && c < C) ? I[(long)r * ldin + c] : 0.f;
    }
    __syncthreads();
#pragma unroll
    for (int i = 0; i < 4; i++) {
        int orow = c0 + threadIdx.y + i * 8, ocol = r0 + threadIdx.x;
        if (orow < C && ocol < R) {
            bf16 h, l;
            split_bf(t[threadIdx.x][threadIdx.y + i * 8], h, l);
            oh[(long)z * sbo + (long)orow * ldo + ocol] = h;
            ol[(long)z * sbo + (long)orow * ldo + ocol] = l;
        }
    }
}

// ---------------- residual add + rmsnorm ----------------
__global__ void k_addnorm(const float* __restrict__ hs, const float* __restrict__ res,
                          const float* __restrict__ w, float* __restrict__ res_out) {
    int t = blockIdx.x;
    __shared__ float red[256];
    float ss = 0.f;
    for (int i = threadIdx.x; i < HH; i += 256) {
        float v = hs[(size_t)t * HH + i] + res[(size_t)t * HH + i];
        res_out[(size_t)t * HH + i] = v;
        ss += v * v;
    }
    red[threadIdx.x] = ss; __syncthreads();
    for (int s = 128; s > 0; s >>= 1) { if (threadIdx.x < s) red[threadIdx.x] += red[threadIdx.x + s]; __syncthreads(); }
    float inv = rsqrtf(red[0] / (float)HH + EPSV);
    for (int i = threadIdx.x; i < HH; i += 256) {
        float v = res_out[(size_t)t * HH + i] * inv * w[i];
        bf16 h, l; split_bf(v, h, l);
        g_xh[(size_t)t * HH + i] = h; g_xl[(size_t)t * HH + i] = l;
    }
}

__global__ void k_norm(const float* __restrict__ in, const float* __restrict__ w) {
    int t = blockIdx.x;
    __shared__ float red[256];
    float ss = 0.f;
    for (int i = threadIdx.x; i < HH; i += 256) { float v = in[(size_t)t * HH + i]; ss += v * v; }
    red[threadIdx.x] = ss; __syncthreads();
    for (int s = 128; s > 0; s >>= 1) { if (threadIdx.x < s) red[threadIdx.x] += red[threadIdx.x + s]; __syncthreads(); }
    float inv = rsqrtf(red[0] / (float)HH + EPSV);
    for (int i = threadIdx.x; i < HH; i += 256) {
        float v = in[(size_t)t * HH + i] * inv * w[i];
        g_x2[(size_t)t * HH + i] = v;
        bf16 h, l; split_bf(v, h, l);
        g_x2h[(size_t)t * HH + i] = h; g_x2l[(size_t)t * HH + i] = l;
    }
}

// ---------------- RoPE ----------------
__global__ void k_rope(const int* __restrict__ pos, const float* __restrict__ qkv) {
    int t = blockIdx.x;
    float fp = (float)pos[t];
    for (int idx = threadIdx.x; idx < (NH + NKV) * 64; idx += 256) {
        int hh = idx >> 6, d = idx & 63;
        float inv = powf(1e6f, -(float)d / 64.f);
        float ang = fp * inv;
        float c = cosf(ang), s = sinf(ang);
        const float* p = qkv + (size_t)t * QKVD + hh * HD;
        float x1 = p[d], x2 = p[d + 64];
        float v1 = x1 * c - x2 * s;
        float v2 = x2 * c + x1 * s;
        bf16 h1, l1, h2, l2;
        split_bf(v1, h1, l1); split_bf(v2, h2, l2);
        if (hh < NH) {
            size_t b = (size_t)t * (NH * HD) + hh * HD;
            g_qh[b + d] = h1; g_ql[b + d] = l1;
            g_qh[b + d + 64] = h2; g_ql[b + d + 64] = l2;
        } else {
            int kv = hh - NH;
            size_t b = (size_t)kv * TT * HD + (size_t)t * HD;
            g_kbh[b + d] = h1; g_kbl[b + d] = l1;
            g_kbh[b + d + 64] = h2; g_kbl[b + d + 64] = l2;
        }
    }
}

// ---------------- MoE gating ----------------
__global__ void k_gate(const float* __restrict__ x2, const float* __restrict__ gw,
                       const float* __restrict__ gb,
                       int* __restrict__ ids, float* __restrict__ ws) {
    int t = blockIdx.x;
    int tid = threadIdx.x, wid = tid >> 5, lane = tid & 31;
    __shared__ float logit[NE];
    for (int e = wid; e < NE; e += 8) {
        float acc = 0.f;
        for (int i = lane; i < HH; i += 32)
            acc += x2[(size_t)t * HH + i] * gw[(size_t)e * HH + i];
#pragma unroll
        for (int o = 16; o > 0; o >>= 1) acc += __shfl_down_sync(0xffffffffu, acc, o);
        if (lane == 0) logit[e] = acc;
    }
    __syncthreads();
    if (tid == 0) {
        float s[NE], sc[NE];
        for (int e = 0; e < NE; e++) { s[e] = 1.f / (1.f + expf(-logit[e])); sc[e] = s[e] + gb[e]; }
        float gscore[NGRP];
        for (int g = 0; g < NGRP; g++) {
            float a = -3.4e38f, b = -3.4e38f;
            for (int j = 0; j < GSZ; j++) {
                float v = sc[g * GSZ + j];
                if (v > a) { b = a; a = v; } else if (v > b) b = v;
            }
            gscore[g] = a + b;
        }
        bool gsel[NGRP] = {false, false, false, false};
        for (int k = 0; k < TGRP; k++) {
            int best = -1; float bv = -3.4e38f;
            for (int g = 0; g < NGRP; g++)
                if (!gsel[g] && gscore[g] > bv) { bv = gscore[g]; best = g; }
            gsel[best] = true;
        }
        bool used[NE];
        for (int e = 0; e < NE; e++) used[e] = !gsel[e / GSZ];
        float tsum = 0.f;
        int pick[TOPK]; float pw[TOPK];
        for (int k = 0; k < TOPK; k++) {
            int best = -1; float bv = -3.4e38f;
            for (int e = 0; e < NE; e++)
                if (!used[e] && sc[e] > bv) { bv = sc[e]; best = e; }
            used[best] = true;
            pick[k] = best; pw[k] = s[best]; tsum += s[best];
        }
        float inv = 1.f / tsum;
        for (int k = 0; k < TOPK; k++) {
            ids[t * TOPK + k] = pick[k];
            ws[t * TOPK + k] = pw[k] * inv;
        }
    }
}

__global__ void k_scatter(const int* __restrict__ ids, const float* __restrict__ ws) {
    int i = blockIdx.x * 256 + threadIdx.x;
    if (i >= TT * TOPK) return;
    int e = ids[i];
    int slot = atomicAdd(&g_cnt[e], 1);
    g_tok[e * TT + slot] = i / TOPK;
    g_wgt[e * TT + slot] = ws[i];
}

// ---------------- launch ----------------
extern "C" void kernel_launch(void* const* d_in, const int* in_sizes, int n_in,
                              void* d_out_, int out_size) {
    const int*   positions = (const int*)d_in[0];
    const float* hs   = (const float*)d_in[1];
    const float* res  = (const float*)d_in[2];
    const float* wln1 = (const float*)d_in[3];
    const float* wln2 = (const float*)d_in[4];
    const float* wqkv = (const float*)d_in[5];
    const float* wo   = (const float*)d_in[6];
    const float* gw   = (const float*)d_in[7];
    const float* gb   = (const float*)d_in[8];
    const float* wgu  = (const float*)d_in[9];
    const float* wd   = (const float*)d_in[10];
    float* out  = (float*)d_out_;
    float* res2 = out + (size_t)TT * HH;

    void* p;
    float *res1, *qkv, *x2, *wgt;
    bf16 *xh, *xl, *x2h, *x2l, *ath, *atl, *acth, *actl, *vth, *vtl;
    bf16 *wqkvh, *wqkvl, *woh, *wol, *wguh, *wgul, *wdh, *wdl;
    int *cnt, *tok, *tkid; float* tkw;
    cudaGetSymbolAddress(&p, g_res1);   res1 = (float*)p;
    cudaGetSymbolAddress(&p, g_qkv);    qkv = (float*)p;
    cudaGetSymbolAddress(&p, g_x2);     x2 = (float*)p;
    cudaGetSymbolAddress(&p, g_xh);  xh = (bf16*)p;  cudaGetSymbolAddress(&p, g_xl);  xl = (bf16*)p;
    cudaGetSymbolAddress(&p, g_x2h); x2h = (bf16*)p; cudaGetSymbolAddress(&p, g_x2l); x2l = (bf16*)p;
    cudaGetSymbolAddress(&p, g_attnh); ath = (bf16*)p; cudaGetSymbolAddress(&p, g_attnl); atl = (bf16*)p;
    cudaGetSymbolAddress(&p, g_acth); acth = (bf16*)p; cudaGetSymbolAddress(&p, g_actl); actl = (bf16*)p;
    cudaGetSymbolAddress(&p, g_vth); vth = (bf16*)p; cudaGetSymbolAddress(&p, g_vtl); vtl = (bf16*)p;
    cudaGetSymbolAddress(&p, g_wqkvh); wqkvh = (bf16*)p; cudaGetSymbolAddress(&p, g_wqkvl); wqkvl = (bf16*)p;
    cudaGetSymbolAddress(&p, g_woh);   woh = (bf16*)p;   cudaGetSymbolAddress(&p, g_wol);   wol = (bf16*)p;
    cudaGetSymbolAddress(&p, g_wguh);  wguh = (bf16*)p;  cudaGetSymbolAddress(&p, g_wgul);  wgul = (bf16*)p;
    cudaGetSymbolAddress(&p, g_wdh);   wdh = (bf16*)p;   cudaGetSymbolAddress(&p, g_wdl);   wdl = (bf16*)p;
    cudaGetSymbolAddress(&p, g_cnt); cnt = (int*)p;
    cudaGetSymbolAddress(&p, g_tok); tok = (int*)p;
    cudaGetSymbolAddress(&p, g_wgt); wgt = (float*)p;
    cudaGetSymbolAddress(&p, g_topk_id); tkid = (int*)p;
    cudaGetSymbolAddress(&p, g_topk_w);  tkw = (float*)p;

    cudaFuncSetAttribute(gemm_m<false, 6>, cudaFuncAttributeMaxDynamicSharedMemorySize, GSM);
    cudaFuncSetAttribute(gemm_m<false, 2>, cudaFuncAttributeMaxDynamicSharedMemorySize, GSM);
    cudaFuncSetAttribute(gemm_m<true,  5>, cudaFuncAttributeMaxDynamicSharedMemorySize, GSM);
    cudaFuncSetAttribute(gemm_m<false, 7>, cudaFuncAttributeMaxDynamicSharedMemorySize, GSM);
    cudaFuncSetAttribute(k_flash, cudaFuncAttributeMaxDynamicSharedMemorySize, FA_SMEM);

    // second stream for weight-convert prepass with per-consumer join events
    cudaStream_t s2;
    cudaStreamCreateWithFlags(&s2, cudaStreamNonBlocking);
    cudaEvent_t evFork, evWo, evWgu, evWd;
    cudaEventCreateWithFlags(&evFork, cudaEventDisableTiming);
    cudaEventCreateWithFlags(&evWo,   cudaEventDisableTiming);
    cudaEventCreateWithFlags(&evWgu,  cudaEventDisableTiming);
    cudaEventCreateWithFlags(&evWd,   cudaEventDisableTiming);

    cudaMemsetAsync(qkv, 0, (size_t)TT * QKVD * sizeof(float));
    cudaMemsetAsync(out, 0, (size_t)TT * HH * sizeof(float));
    cudaMemsetAsync(cnt, 0, NE * sizeof(int));

    cudaEventRecord(evFork, 0);
    cudaStreamWaitEvent(s2, evFork, 0);
    // s2: converts ordered by consumer (wo first, wd last)
    { long n = (long)HH * HH;   k_conv<<<(unsigned)((n / 16 + 255) / 256), 256, 0, s2>>>(wo, woh, wol, n); }
    cudaEventRecord(evWo, s2);
    { long n = (long)NE * HH * (IM / 16); k_conv_gu<<<(unsigned)((n + 255) / 256), 256, 0, s2>>>(wgu, wguh, wgul); }
    cudaEventRecord(evWgu, s2);
    { long n = (long)NE * IM * HH; k_conv<<<(unsigned)((n / 16 + 255) / 256), 256, 0, s2>>>(wd, wdh, wdl, n); }
    cudaEventRecord(evWd, s2);

    // main stream
    { long n = (long)HH * QKVD; k_conv<<<(unsigned)((n / 16 + 255) / 256), 256>>>(wqkv, wqkvh, wqkvl, n); }
    k_addnorm<<<TT, 256>>>(hs, res, wln1, res1);

    // qkv = x @ wqkv  (split-K=3, atomicAdd epilogue)
    { dim3 g(QKVD / BNT, TT / BMT, 3);
      gemm_m<false, 6><<<g, 256, GSM>>>(
          xh, xl, HH, 0, wqkvh, wqkvl, QKVD, 0, 1,
          qkv, nullptr, nullptr, QKVD, 0, TT, QKVD, HH,
          nullptr, nullptr, 0, nullptr, 0, 1.f); }

    // rope ; V transpose+convert
    k_rope<<<TT, 256>>>(positions, qkv);
    { dim3 g(HD / 32, TT / 32, NKV);
      k_tconv<<<g, dim3(32, 8)>>>(qkv + (NH + NKV) * HD, QKVD, HD, vth, vtl, TT, (long)HD * TT, TT, HD); }

    // flash attention
    { dim3 g(NH, TT / 128); k_flash<<<g, 256, FA_SMEM>>>(); }

    // res2 = attn @ wo + res1  (needs wo convert only)
    cudaStreamWaitEvent(0, evWo, 0);
    { dim3 g(HH / BNT, TT / BMT, 1);
      gemm_m<false, 2><<<g, 256, GSM>>>(
          ath, atl, HH, 0, woh, wol, HH, 0, 1,
          res2, nullptr, nullptr, HH, 0, TT, HH, HH,
          nullptr, nullptr, 0, res1, 0, 1.f); }

    // x2 = rmsnorm(res2)
    k_norm<<<TT, 256>>>(res2, wln2);

    // gating + scatter
    k_gate<<<TT, 256>>>(x2, gw, gb, tkid, tkw);
    k_scatter<<<(TT * TOPK + 255) / 256, 256>>>(tkid, tkw);

    // per-expert gate_up + fused silu  (needs wgu convert)
    cudaStreamWaitEvent(0, evWgu, 0);
    { dim3 g((2 * IM) / BNT, TT / BMT, NE);
      gemm_m<true, 5><<<g, 256, GSM>>>(
          x2h, x2l, HH, 0, wguh, wgul, 2 * IM, (long)HH * 2 * IM, 1,
          nullptr, acth, actl, IM, (long)TT * IM, TT, 2 * IM, HH,
          cnt, tok, TT, nullptr, 0, 1.f); }

    // per-expert down + weighted scatter-add (split-K=2; needs wd convert)
    cudaStreamWaitEvent(0, evWd, 0);
    { dim3 g(HH / BNT, TT / BMT, NE * 2);
      gemm_m<false, 7><<<g, 256, GSM>>>(
          acth, actl, IM, (long)TT * IM, wdh, wdl, HH, (long)IM * HH, 1,
          out, nullptr, nullptr, HH, 0, TT, HH, IM,
          cnt, tok, TT, wgt, TT, 1.f); }

    cudaEventDestroy(evFork);
    cudaEventDestroy(evWo);
    cudaEventDestroy(evWgu);
    cudaEventDestroy(evWd);
    cudaStreamDestroy(s2);
}

// round 14
// speedup vs baseline: 1.2036x; 1.2036x over previous
#include <cuda_runtime.h>
#include <cuda_bf16.h>
#include <cuda_fp16.h>
#include <math.h>
#include <stdint.h>

#define TT 2048
#define HH 2048
#define NH 16
#define NKV 4
#define HD 128
#define NE 16
#define TOPK 4
#define NGRP 4
#define GSZ 4
#define TGRP 2
#define IM 1024
#define QKVD 3072
#define ATT_SCALE 0.08838834764831845f
#define EPSV 1e-6f

typedef __nv_bfloat16 bf16;

// ---------------- scratch (device globals; no allocations) ----------------
__device__ float g_res1[(size_t)TT * HH];
__device__ float g_qkv[(size_t)TT * QKVD];
__device__ float g_x2[(size_t)TT * HH];
__device__ bf16  g_xh[(size_t)TT * HH],  g_xl[(size_t)TT * HH];
__device__ bf16  g_x2h[(size_t)TT * HH], g_x2l[(size_t)TT * HH];      // holds fp16 bits
__device__ bf16  g_qh[(size_t)TT * (NH * HD)], g_ql[(size_t)TT * (NH * HD)];
__device__ bf16  g_attnh[(size_t)TT * HH], g_attnl[(size_t)TT * HH];
__device__ bf16  g_acth[(size_t)NE * TT * IM], g_actl[(size_t)NE * TT * IM]; // fp16 bits
__device__ bf16  g_kbh[(size_t)NKV * TT * HD], g_kbl[(size_t)NKV * TT * HD];
__device__ bf16  g_vth[(size_t)NKV * HD * TT], g_vtl[(size_t)NKV * HD * TT];
__device__ bf16  g_wqkvh[(size_t)HH * QKVD], g_wqkvl[(size_t)HH * QKVD];
__device__ bf16  g_woh[(size_t)HH * HH],     g_wol[(size_t)HH * HH];
__device__ bf16  g_wguh[(size_t)NE * HH * 2 * IM];                    // fp16 bits (single)
__device__ bf16  g_wdh[(size_t)NE * IM * HH];                         // fp16 bits (single)
__device__ int   g_cnt[NE];
__device__ int   g_tok[NE * TT];
__device__ float g_wgt[NE * TT];
__device__ int   g_topk_id[TT * TOPK];
__device__ float g_topk_w[TT * TOPK];

// ---------------- helpers ----------------
__device__ __forceinline__ uint32_t smem_u32(const void* p) {
    uint32_t a;
    asm("{ .reg .u64 t; cvta.to.shared.u64 t, %1; cvt.u32.u64 %0, t; }" : "=r"(a) : "l"(p));
    return a;
}
__device__ __forceinline__ void split_bf(float v, bf16& h, bf16& l) {
    h = __float2bfloat16_rn(v);
    l = __float2bfloat16_rn(v - __bfloat162float(h));
}
__device__ __forceinline__ void split_hf(float v, __half& h, __half& l) {
    h = __float2half_rn(v);
    l = __float2half_rn(v - __half2float(h));
}
__device__ __forceinline__ uint32_t pack2(bf16 a, bf16 b) {
    return (uint32_t)__bfloat16_as_ushort(a) | ((uint32_t)__bfloat16_as_ushort(b) << 16);
}
__device__ __forceinline__ uint32_t pack2h(__half a, __half b) {
    return (uint32_t)__half_as_ushort(a) | ((uint32_t)__half_as_ushort(b) << 16);
}
__device__ __forceinline__ void cpa(uint32_t d, const void* s, int sz) {
    asm volatile("cp.async.cg.shared.global [%0], [%1], 16, %2;" :: "r"(d), "l"(s), "r"(sz));
}
__device__ __forceinline__ void cpcommit() { asm volatile("cp.async.commit_group;" ::: "memory"); }
__device__ __forceinline__ void cpwaitN(int n) {
    if (n == 0)      asm volatile("cp.async.wait_group 0;" ::: "memory");
    else if (n == 1) asm volatile("cp.async.wait_group 1;" ::: "memory");
    else             asm volatile("cp.async.wait_group 2;" ::: "memory");
}
__device__ __forceinline__ void ldm4(uint32_t* r, uint32_t a) {
    asm volatile("ldmatrix.sync.aligned.m8n8.x4.shared.b16 {%0,%1,%2,%3}, [%4];"
                 : "=r"(r[0]), "=r"(r[1]), "=r"(r[2]), "=r"(r[3]) : "r"(a));
}
__device__ __forceinline__ void ldm4t(uint32_t* r, uint32_t a) {
    asm volatile("ldmatrix.sync.aligned.m8n8.x4.trans.shared.b16 {%0,%1,%2,%3}, [%4];"
                 : "=r"(r[0]), "=r"(r[1]), "=r"(r[2]), "=r"(r[3]) : "r"(a));
}
// non-volatile — lets ptxas schedule MMAs for ILP.
__device__ __forceinline__ void mma16816(float* c, const uint32_t* a, const uint32_t* b) {
    asm("mma.sync.aligned.m16n8k16.row.col.f32.bf16.bf16.f32 "
        "{%0,%1,%2,%3},{%4,%5,%6,%7},{%8,%9},{%0,%1,%2,%3};"
        : "+f"(c[0]), "+f"(c[1]), "+f"(c[2]), "+f"(c[3])
        : "r"(a[0]), "r"(a[1]), "r"(a[2]), "r"(a[3]), "r"(b[0]), "r"(b[1]));
}
__device__ __forceinline__ void mma16816h(float* c, const uint32_t* a, const uint32_t* b) {
    asm("mma.sync.aligned.m16n8k16.row.col.f32.f16.f16.f32 "
        "{%0,%1,%2,%3},{%4,%5,%6,%7},{%8,%9},{%0,%1,%2,%3};"
        : "+f"(c[0]), "+f"(c[1]), "+f"(c[2]), "+f"(c[3])
        : "r"(a[0]), "r"(a[1]), "r"(a[2]), "r"(a[3]), "r"(b[0]), "r"(b[1]));
}

// ---------------- mma.sync GEMM (B K-major, 3-stage, ILP-ordered MMAs) ------------
// F16B=false: bf16x3 (A hi/lo x B hi/lo, 3 terms). F16B=true: fp16 A hi/lo x single
// fp16 B, 2 terms (MoE only — downstream of all decision points).
// EPI: 0 fp32 store, 2 add X, 3 atomicAdd scatter, 5 silu(even)*odd -> fp16 hi/lo,
//      6 split-K (z = slice, batch 0), 7 split-K x2 + scatter (z = expert*2+slice).
#define BMT 128
#define BNT 128
#define BKT 32
#define AST 80u
#define BST 272u
#define A_SZ 10240u
#define B_SZ 8704u
#define STG2 (2u * A_SZ + 2u * B_SZ)   // 37888
#define NSTG 3
#define GSM (NSTG * 37888)             // 113664

template <bool GA, int EPI, bool F16B>
__global__ void __launch_bounds__(256, 2)
gemm_m(const bf16* __restrict__ Ah0, const bf16* __restrict__ Al0, int lda, long saz,
       const bf16* __restrict__ Bh0, const bf16* __restrict__ Bl0, int ldb, long sbz, int bdiv,
       float* __restrict__ C0, bf16* __restrict__ Oh0, bf16* __restrict__ Ol0, int ldc, long scz,
       int M0, int N, int K,
       const int* __restrict__ Mptr, const int* __restrict__ gidx0, int sgz,
       const float* __restrict__ X0, long sxz, float alpha) {
    int z = blockIdx.z;
    int zb = z, ksl = 0, kns = 1;
    if (EPI == 6) { zb = 0; ksl = z; kns = (int)gridDim.z; }
    if (EPI == 7) { zb = z >> 1; ksl = z & 1; kns = 2; }
    int M = Mptr ? Mptr[zb] : M0;
    int row0 = blockIdx.y * BMT, col0 = blockIdx.x * BNT;
    if (row0 >= M) return;

    extern __shared__ char smem[];
    uint32_t sb = smem_u32(smem);
    int tid = threadIdx.x, lane = tid & 31, wid = tid >> 5;
    const int m0w = (wid & 3) * 32, n0w = (wid >> 2) * 64;

    const int* gidxz = (GA || EPI == 3 || EPI == 7) ? gidx0 + (long)zb * sgz : nullptr;
    const float* X = (EPI == 2 || EPI == 3 || EPI == 7) ? X0 + (long)zb * sxz : nullptr;
    const bf16* Bh = Bh0 + (long)(zb / bdiv) * sbz + col0;
    const bf16* Bl = F16B ? nullptr : (Bl0 + (long)(zb / bdiv) * sbz + col0);

    int nchTot = K / BKT;
    int c0 = (nchTot * ksl) / kns;
    int c1 = (nchTot * (ksl + 1)) / kns;

    int lrow = tid >> 1, lhalf = tid & 1;
    int ari = row0 + lrow;
    bool av = ari < M;
    long agrow = ari;
    if (GA) agrow = av ? (long)gidxz[ari] : 0;
    long arow2 = (GA ? agrow : (long)ari);
    const bf16* agh2 = Ah0 + (long)zb * saz + arow2 * (long)lda;
    const bf16* agl2 = Al0 + (long)zb * saz + arow2 * (long)lda;
    int asz = av ? 16 : 0;
    uint32_t dst_a = sb + lrow * AST + lhalf * 32;
    int brow = tid >> 3, bth = tid & 7;
    uint32_t dst_b = sb + 2 * A_SZ + brow * BST + bth * 32;

    auto cp_stage = [&](int buf, int k0) {
        uint32_t so = buf * STG2;
        long ko = k0 + lhalf * 16;
        cpa(dst_a + so,             agh2 + ko,     asz);
        cpa(dst_a + so + 16,        agh2 + ko + 8, asz);
        cpa(dst_a + so + A_SZ,      agl2 + ko,     asz);
        cpa(dst_a + so + A_SZ + 16, agl2 + ko + 8, asz);
        long bko = (long)(k0 + brow) * ldb + bth * 16;
        cpa(dst_b + so,             Bh + bko,     16);
        cpa(dst_b + so + 16,        Bh + bko + 8, 16);
        if (!F16B) {
            cpa(dst_b + so + B_SZ,      Bl + bko,     16);
            cpa(dst_b + so + B_SZ + 16, Bl + bko + 8, 16);
        }
    };

    float acc[2][8][4];
#pragma unroll
    for (int i = 0; i < 2; i++)
#pragma unroll
        for (int j = 0; j < 8; j++)
#pragma unroll
            for (int q = 0; q < 4; q++) acc[i][j][q] = 0.f;

    uint32_t a_off = (uint32_t)(m0w + (lane & 15)) * AST + (uint32_t)(lane >> 4) * 16;
    uint32_t b_off = (uint32_t)((lane & 7) + ((lane >> 3) & 1) * 8) * BST
                   + (uint32_t)(lane >> 4) * 16;

    auto compute = [&](int buf) {
        uint32_t ab  = sb + buf * STG2;
        uint32_t alb = ab + A_SZ;
        uint32_t bhb = ab + 2 * A_SZ;
        uint32_t blb = bhb + B_SZ;
#pragma unroll
        for (int s = 0; s < 2; s++) {
            uint32_t ka = s * 32;
            uint32_t ah0[4], ah1[4], al0[4], al1[4];
            ldm4(ah0, ab + a_off + ka);
            ldm4(ah1, ab + a_off + 16 * AST + ka);
            ldm4(al0, alb + a_off + ka);
            ldm4(al1, alb + a_off + 16 * AST + ka);
            uint32_t bs = b_off + s * (16 * BST);
#pragma unroll
            for (int np = 0; np < 4; np++) {
                uint32_t bo = bs + (uint32_t)((n0w + np * 16) * 2);
                int ne = 2 * np, no = 2 * np + 1;
                if (F16B) {
                    uint32_t bh[4];
                    ldm4t(bh, bhb + bo);
                    mma16816h(acc[0][ne], ah0, bh);  mma16816h(acc[0][no], ah0, bh + 2);
                    mma16816h(acc[1][ne], ah1, bh);  mma16816h(acc[1][no], ah1, bh + 2);
                    mma16816h(acc[0][ne], al0, bh);  mma16816h(acc[0][no], al0, bh + 2);
                    mma16816h(acc[1][ne], al1, bh);  mma16816h(acc[1][no], al1, bh + 2);
                } else {
                    uint32_t bh[4], bl[4];
                    ldm4t(bh, bhb + bo);
                    ldm4t(bl, blb + bo);
                    mma16816(acc[0][ne], ah0, bh);     mma16816(acc[0][no], ah0, bh + 2);
                    mma16816(acc[1][ne], ah1, bh);     mma16816(acc[1][no], ah1, bh + 2);
                    mma16816(acc[0][ne], ah0, bl);     mma16816(acc[0][no], ah0, bl + 2);
                    mma16816(acc[1][ne], ah1, bl);     mma16816(acc[1][no], ah1, bl + 2);
                    mma16816(acc[0][ne], al0, bh);     mma16816(acc[0][no], al0, bh + 2);
                    mma16816(acc[1][ne], al1, bh);     mma16816(acc[1][no], al1, bh + 2);
                }
            }
        }
    };

    cp_stage(0, c0 * BKT); cpcommit();
    cp_stage(1, (c0 + 1) * BKT); cpcommit();
    int buf = 0;
    for (int c = c0; c < c1; c++) {
        cpwaitN(1);
        __syncthreads();
        compute(buf);
        int nb = buf + 1; if (nb == NSTG) nb = 0;
        int pb = buf + 2; if (pb >= NSTG) pb -= NSTG;
        if (c + 2 < c1) cp_stage(pb, (c + 2) * BKT);
        cpcommit();
        buf = nb;
    }

    // epilogue
    int lq = lane >> 2, lr = lane & 3;
#pragma unroll
    for (int mt = 0; mt < 2; mt++) {
        int r0 = row0 + m0w + mt * 16 + lq;
        int r1 = r0 + 8;
#pragma unroll
        for (int nt = 0; nt < 8; nt++) {
            long cc = (long)col0 + n0w + nt * 8 + 2 * lr;
            float v0 = acc[mt][nt][0] * alpha, v1 = acc[mt][nt][1] * alpha;
            float v2 = acc[mt][nt][2] * alpha, v3 = acc[mt][nt][3] * alpha;
            if (EPI == 6) {
                float* C = C0;
                if (r0 < M) {
                    atomicAdd(&C[(long)r0 * ldc + cc], v0);
                    atomicAdd(&C[(long)r0 * ldc + cc + 1], v1);
                }
                if (r1 < M) {
                    atomicAdd(&C[(long)r1 * ldc + cc], v2);
                    atomicAdd(&C[(long)r1 * ldc + cc + 1], v3);
                }
            } else if (EPI == 3 || EPI == 7) {
                float* C = C0 + (EPI == 3 ? (long)zb * scz : 0);
                if (r0 < M) {
                    long gr = gidxz[r0]; float w = X[r0];
                    atomicAdd(&C[gr * ldc + cc], w * v0);
                    atomicAdd(&C[gr * ldc + cc + 1], w * v1);
                }
                if (r1 < M) {
                    long gr = gidxz[r1]; float w = X[r1];
                    atomicAdd(&C[gr * ldc + cc], w * v2);
                    atomicAdd(&C[gr * ldc + cc + 1], w * v3);
                }
            } else if (EPI == 5) {
                __half* oh = (__half*)(Oh0 + (long)zb * scz);
                __half* ol = (__half*)(Ol0 + (long)zb * scz);
                long co = cc >> 1;
                if (r0 < M) {
                    float a = v0 / (1.f + expf(-v0)) * v1;
                    __half h, l; split_hf(a, h, l);
                    oh[(long)r0 * ldc + co] = h; ol[(long)r0 * ldc + co] = l;
                }
                if (r1 < M) {
                    float a = v2 / (1.f + expf(-v2)) * v3;
                    __half h, l; split_hf(a, h, l);
                    oh[(long)r1 * ldc + co] = h; ol[(long)r1 * ldc + co] = l;
                }
            } else if (EPI == 2) {
                float* C = C0 + (long)zb * scz;
                if (r0 < M) {
                    float2 xv = *(const float2*)&X[(long)r0 * ldc + cc];
                    *(float2*)&C[(long)r0 * ldc + cc] = make_float2(v0 + xv.x, v1 + xv.y);
                }
                if (r1 < M) {
                    float2 xv = *(const float2*)&X[(long)r1 * ldc + cc];
                    *(float2*)&C[(long)r1 * ldc + cc] = make_float2(v2 + xv.x, v3 + xv.y);
                }
            } else {
                float* C = C0 + (long)zb * scz;
                if (r0 < M) *(float2*)&C[(long)r0 * ldc + cc] = make_float2(v0, v1);
                if (r1 < M) *(float2*)&C[(long)r1 * ldc + cc] = make_float2(v2, v3);
            }
        }
    }
}

// ---------------- flash attention (bf16x3, online softmax) ----------------
#define FA_Q  0u
#define FA_QL 40960u
#define FA_K  81920u
#define FA_KL 122880u
#define FA_V  163840u
#define FA_VL 184320u
#define FA_SMEM 204800

__global__ void __launch_bounds__(256, 1) k_flash() {
    extern __shared__ char smem[];
    uint32_t sb = smem_u32(smem);
    int head = blockIdx.x;
    int qb = (int)gridDim.y - 1 - (int)blockIdx.y;
    int row0 = qb * 128;
    int kv = head >> 2;
    int tid = threadIdx.x, lane = tid & 31, w = tid >> 5;
    int lq = lane >> 2, lr = lane & 3;
    int lrow = tid >> 1, lhalf = tid & 1;

    const bf16* qgh = g_qh + (size_t)(row0 + lrow) * (NH * HD) + head * HD + lhalf * 16;
    const bf16* qgl = g_ql + (size_t)(row0 + lrow) * (NH * HD) + head * HD + lhalf * 16;
    const bf16* kgh = g_kbh + (size_t)kv * TT * HD + (size_t)lrow * HD + lhalf * 16;
    const bf16* kgl = g_kbl + (size_t)kv * TT * HD + (size_t)lrow * HD + lhalf * 16;
    const bf16* vgh = g_vth + (size_t)kv * HD * TT + (size_t)lrow * TT + lhalf * 16;
    const bf16* vgl = g_vtl + (size_t)kv * HD * TT + (size_t)lrow * TT + lhalf * 16;

#pragma unroll
    for (int c = 0; c < 4; c++) {
        uint32_t d = sb + FA_Q + (uint32_t)((c * 128 + lrow) * 80) + lhalf * 32;
        cpa(d, qgh + c * 32, 16); cpa(d + 16, qgh + c * 32 + 8, 16);
        uint32_t dl = d + (FA_QL - FA_Q);
        cpa(dl, qgl + c * 32, 16); cpa(dl + 16, qgl + c * 32 + 8, 16);
    }
    cpcommit();

    auto issueK = [&](int s0) {
#pragma unroll
        for (int c = 0; c < 4; c++) {
            uint32_t d = sb + FA_K + (uint32_t)((c * 128 + lrow) * 80) + lhalf * 32;
            const bf16* s = kgh + (size_t)s0 * HD + c * 32;
            cpa(d, s, 16); cpa(d + 16, s + 8, 16);
            uint32_t dl = d + (FA_KL - FA_K);
            const bf16* sl = kgl + (size_t)s0 * HD + c * 32;
            cpa(dl, sl, 16); cpa(dl + 16, sl + 8, 16);
        }
        cpcommit();
    };
    auto issueV = [&](int s0, int c) {
        uint32_t d = sb + FA_V + (uint32_t)(((c & 1) * 128 + lrow) * 80) + lhalf * 32;
        const bf16* s = vgh + s0 + c * 32;
        cpa(d, s, 16); cpa(d + 16, s + 8, 16);
        uint32_t dl = d + (FA_VL - FA_V);
        const bf16* sl = vgl + s0 + c * 32;
        cpa(dl, sl, 16); cpa(dl + 16, sl + 8, 16);
        cpcommit();
    };
    issueK(0);

    float O[16][4];
#pragma unroll
    for (int i = 0; i < 16; i++) { O[i][0] = O[i][1] = O[i][2] = O[i][3] = 0.f; }
    float m_lo = -1e30f, m_hi = -1e30f, l_lo = 0.f, l_hi = 0.f;
    int ntl = qb + 1;
    uint32_t a_off = (uint32_t)((w * 16 + (lane & 15)) * 80) + (uint32_t)(lane >> 4) * 16;
    uint32_t b_off = (uint32_t)((((lane >> 4) << 3) + (lane & 7)) * 80) + (uint32_t)((lane >> 3) & 1) * 16;

    for (int st = 0; st < ntl; st++) {
        int s0 = st * 128;
        __syncthreads();
        issueV(s0, 0); issueV(s0, 1);
        asm volatile("cp.async.wait_group 2;" ::: "memory");
        __syncthreads();

        float S[16][4];
#pragma unroll
        for (int i = 0; i < 16; i++) { S[i][0] = S[i][1] = S[i][2] = S[i][3] = 0.f; }
#pragma unroll
        for (int kc = 0; kc < 4; kc++)
#pragma unroll
        for (int ks = 0; ks < 2; ks++) {
            uint32_t qa = sb + (uint32_t)(kc * 128 * 80) + a_off + ks * 32;
            uint32_t ah[4], al[4];
            ldm4(ah, qa + FA_Q);
            ldm4(al, qa + FA_QL);
#pragma unroll
            for (int j = 0; j < 8; j++) {
                uint32_t kb = sb + FA_K + (uint32_t)((kc * 128 + 16 * j) * 80) + b_off + ks * 32;
                uint32_t bh[4], bl[4];
                ldm4(bh, kb); ldm4(bl, kb + (FA_KL - FA_K));
                mma16816(S[2 * j],     ah, bh);     mma16816(S[2 * j + 1], ah, bh + 2);
                mma16816(S[2 * j],     ah, bl);     mma16816(S[2 * j + 1], ah, bl + 2);
                mma16816(S[2 * j],     al, bh);     mma16816(S[2 * j + 1], al, bh + 2);
            }
        }

        bool dg = (st == qb);
        int rlo = row0 + w * 16 + lq, rhi = rlo + 8;
#pragma unroll
        for (int nt = 0; nt < 16; nt++) {
            int cbase = s0 + nt * 8 + 2 * lr;
#pragma unroll
            for (int q = 0; q < 4; q++) {
                float v = S[nt][q] * ATT_SCALE;
                int col = cbase + (q & 1);
                int rw = (q < 2) ? rlo : rhi;
                if (dg && col > rw) v = -1e30f;
                S[nt][q] = v;
            }
        }
        float mx0 = -1e30f, mx1 = -1e30f;
#pragma unroll
        for (int nt = 0; nt < 16; nt++) {
            mx0 = fmaxf(mx0, fmaxf(S[nt][0], S[nt][1]));
            mx1 = fmaxf(mx1, fmaxf(S[nt][2], S[nt][3]));
        }
        mx0 = fmaxf(mx0, __shfl_xor_sync(0xffffffffu, mx0, 1));
        mx0 = fmaxf(mx0, __shfl_xor_sync(0xffffffffu, mx0, 2));
        mx1 = fmaxf(mx1, __shfl_xor_sync(0xffffffffu, mx1, 1));
        mx1 = fmaxf(mx1, __shfl_xor_sync(0xffffffffu, mx1, 2));
        float mn0 = fmaxf(m_lo, mx0), mn1 = fmaxf(m_hi, mx1);
        float sc0 = expf(m_lo - mn0), sc1 = expf(m_hi - mn1);
        float rs0 = 0.f, rs1 = 0.f;
#pragma unroll
        for (int nt = 0; nt < 16; nt++) {
            S[nt][0] = expf(S[nt][0] - mn0); S[nt][1] = expf(S[nt][1] - mn0);
            S[nt][2] = expf(S[nt][2] - mn1); S[nt][3] = expf(S[nt][3] - mn1);
            rs0 += S[nt][0] + S[nt][1];
            rs1 += S[nt][2] + S[nt][3];
        }
        rs0 += __shfl_xor_sync(0xffffffffu, rs0, 1); rs0 += __shfl_xor_sync(0xffffffffu, rs0, 2);
        rs1 += __shfl_xor_sync(0xffffffffu, rs1, 1); rs1 += __shfl_xor_sync(0xffffffffu, rs1, 2);
        l_lo = l_lo * sc0 + rs0; l_hi = l_hi * sc1 + rs1;
        m_lo = mn0; m_hi = mn1;
#pragma unroll
        for (int nt = 0; nt < 16; nt++) {
            O[nt][0] *= sc0; O[nt][1] *= sc0; O[nt][2] *= sc1; O[nt][3] *= sc1;
        }

        __syncthreads();
        bool haveK = (st + 1 < ntl);
        if (haveK) issueK(s0 + 128);

#pragma unroll 1
        for (int c = 0; c < 4; c++) {
            int pend = haveK ? (c <= 1 ? 2 : (c == 2 ? 1 : 0)) : (c < 3 ? 1 : 0);
            cpwaitN(pend);
            __syncthreads();
#pragma unroll
            for (int ks = 0; ks < 2; ks++) {
                int t0 = 2 * (2 * c + ks), t1 = t0 + 1;
                uint32_t pah[4], pal[4];
                bf16 h0, l0, h1, l1;
                split_bf(S[t0][0], h0, l0); split_bf(S[t0][1], h1, l1);
                pah[0] = pack2(h0, h1); pal[0] = pack2(l0, l1);
                split_bf(S[t0][2], h0, l0); split_bf(S[t0][3], h1, l1);
                pah[1] = pack2(h0, h1); pal[1] = pack2(l0, l1);
                split_bf(S[t1][0], h0, l0); split_bf(S[t1][1], h1, l1);
                pah[2] = pack2(h0, h1); pal[2] = pack2(l0, l1);
                split_bf(S[t1][2], h0, l0); split_bf(S[t1][3], h1, l1);
                pah[3] = pack2(h0, h1); pal[3] = pack2(l0, l1);
#pragma unroll
                for (int j = 0; j < 8; j++) {
                    uint32_t vb = sb + FA_V + (uint32_t)((((c & 1) * 128) + 16 * j) * 80) + b_off + ks * 32;
                    uint32_t vh[4], vl[4];
                    ldm4(vh, vb); ldm4(vl, vb + (FA_VL - FA_V));
                    mma16816(O[2 * j],     pah, vh);     mma16816(O[2 * j + 1], pah, vh + 2);
                    mma16816(O[2 * j],     pah, vl);     mma16816(O[2 * j + 1], pah, vl + 2);
                    mma16816(O[2 * j],     pal, vh);     mma16816(O[2 * j + 1], pal, vh + 2);
                }
            }
            __syncthreads();
            if (c + 2 < 4) issueV(s0, c + 2);
        }
    }

    float il0 = 1.f / l_lo, il1 = 1.f / l_hi;
    int rlo = row0 + w * 16 + lq, rhi = rlo + 8;
#pragma unroll
    for (int nt = 0; nt < 16; nt++) {
        long col = (long)head * HD + nt * 8 + 2 * lr;
        bf16 h0, l0, h1, l1;
        float v0 = O[nt][0] * il0, v1 = O[nt][1] * il0;
        split_bf(v0, h0, l0); split_bf(v1, h1, l1);
        *(uint32_t*)&g_attnh[(long)rlo * HH + col] = pack2(h0, h1);
        *(uint32_t*)&g_attnl[(long)rlo * HH + col] = pack2(l0, l1);
        float v2 = O[nt][2] * il1, v3 = O[nt][3] * il1;
        split_bf(v2, h0, l0); split_bf(v3, h1, l1);
        *(uint32_t*)&g_attnh[(long)rhi * HH + col] = pack2(h0, h1);
        *(uint32_t*)&g_attnl[(long)rhi * HH + col] = pack2(l0, l1);
    }
}

// ---------------- streaming convert fp32 -> bf16 hi/lo (8 elems/thread) -----------
__global__ void k_conv(const float* __restrict__ in, bf16* __restrict__ oh,
                       bf16* __restrict__ ol, long n) {
    long i = ((long)blockIdx.x * 256 + threadIdx.x) * 8;
    if (i >= n) return;
    float4 a = *(const float4*)(in + i);
    float4 b = *(const float4*)(in + i + 4);
    bf16 h0, l0, h1, l1;
    uint32_t H[4], L[4];
    split_bf(a.x, h0, l0); split_bf(a.y, h1, l1); H[0] = pack2(h0, h1); L[0] = pack2(l0, l1);
    split_bf(a.z, h0, l0); split_bf(a.w, h1, l1); H[1] = pack2(h0, h1); L[1] = pack2(l0, l1);
    split_bf(b.x, h0, l0); split_bf(b.y, h1, l1); H[2] = pack2(h0, h1); L[2] = pack2(l0, l1);
    split_bf(b.z, h0, l0); split_bf(b.w, h1, l1); H[3] = pack2(h0, h1); L[3] = pack2(l0, l1);
    *(uint4*)(oh + i) = make_uint4(H[0], H[1], H[2], H[3]);
    *(uint4*)(ol + i) = make_uint4(L[0], L[1], L[2], L[3]);
}

// fp32 -> single fp16 (8 elems/thread) for wd
__global__ void k_convh(const float* __restrict__ in, bf16* __restrict__ oh, long n) {
    long i = ((long)blockIdx.x * 256 + threadIdx.x) * 8;
    if (i >= n) return;
    float4 a = *(const float4*)(in + i);
    float4 b = *(const float4*)(in + i + 4);
    uint32_t H[4];
    H[0] = pack2h(__float2half_rn(a.x), __float2half_rn(a.y));
    H[1] = pack2h(__float2half_rn(a.z), __float2half_rn(a.w));
    H[2] = pack2h(__float2half_rn(b.x), __float2half_rn(b.y));
    H[3] = pack2h(__float2half_rn(b.z), __float2half_rn(b.w));
    *(uint4*)(oh + i) = make_uint4(H[0], H[1], H[2], H[3]);
}

// gate/up column interleave, single fp16 (8 gate + 8 up per thread)
__global__ void k_conv_guh(const float* __restrict__ in, bf16* __restrict__ oh) {
    long t = (long)blockIdx.x * 256 + threadIdx.x;
    long rows = (long)NE * HH;
    long perRow = IM / 8;
    if (t >= rows * perRow) return;
    long row = t / perRow;
    long c = (t % perRow) * 8;
    const float* base = in + row * (2 * IM);
    float4 gA = *(const float4*)(base + c);
    float4 gB = *(const float4*)(base + c + 4);
    float4 uA = *(const float4*)(base + IM + c);
    float4 uB = *(const float4*)(base + IM + c + 4);
    uint32_t H[8];
    H[0] = pack2h(__float2half_rn(gA.x), __float2half_rn(uA.x));
    H[1] = pack2h(__float2half_rn(gA.y), __float2half_rn(uA.y));
    H[2] = pack2h(__float2half_rn(gA.z), __float2half_rn(uA.z));
    H[3] = pack2h(__float2half_rn(gA.w), __float2half_rn(uA.w));
    H[4] = pack2h(__float2half_rn(gB.x), __float2half_rn(uB.x));
    H[5] = pack2h(__float2half_rn(gB.y), __float2half_rn(uB.y));
    H[6] = pack2h(__float2half_rn(gB.z), __float2half_rn(uB.z));
    H[7] = pack2h(__float2half_rn(gB.w), __float2half_rn(uB.w));
    bf16* po = oh + row * (2 * IM) + 2 * c;
    *(uint4*)po       = make_uint4(H[0], H[1], H[2], H[3]);
    *(uint4*)(po + 8) = make_uint4(H[4], H[5], H[6], H[7]);
}

// ---------------- transpose + convert (V only) ----------------
__global__ void k_tconv(const float* __restrict__ in, long ldin, long sbin,
                        bf16* __restrict__ oh, bf16* __restrict__ ol, long ldo, long sbo,
                        int R, int C) {
    __shared__ float t[32][33];
    int z = blockIdx.z;
    const float* I = in + (long)z * sbin;
    int c0 = blockIdx.x * 32, r0 = blockIdx.y * 32;
#pragma unroll
    for (int i = 0; i < 4; i++) {
        int r = r0 + threadIdx.y + i * 8, c = c0 + threadIdx.x;
        t[threadIdx.y + i * 8][threadIdx.x] = (r < R && c < C) ? I[(long)r * ldin + c] : 0.f;
    }
    __syncthreads();
#pragma unroll
    for (int i = 0; i < 4; i++) {
        int orow = c0 + threadIdx.y + i * 8, ocol = r0 + threadIdx.x;
        if (orow < C && ocol < R) {
            bf16 h, l;
            split_bf(t[threadIdx.x][threadIdx.y + i * 8], h, l);
            oh[(long)z * sbo + (long)orow * ldo + ocol] = h;
            ol[(long)z * sbo + (long)orow * ldo + ocol] = l;
        }
    }
}

// ---------------- residual add + rmsnorm ----------------
__global__ void k_addnorm(const float* __restrict__ hs, const float* __restrict__ res,
                          const float* __restrict__ w, float* __restrict__ res_out) {
    int t = blockIdx.x;
    __shared__ float red[256];
    float ss = 0.f;
    for (int i = threadIdx.x; i < HH; i += 256) {
        float v = hs[(size_t)t * HH + i] + res[(size_t)t * HH + i];
        res_out[(size_t)t * HH + i] = v;
        ss += v * v;
    }
    red[threadIdx.x] = ss; __syncthreads();
    for (int s = 128; s > 0; s >>= 1) { if (threadIdx.x < s) red[threadIdx.x] += red[threadIdx.x + s]; __syncthreads(); }
    float inv = rsqrtf(red[0] / (float)HH + EPSV);
    for (int i = threadIdx.x; i < HH; i += 256) {
        float v = res_out[(size_t)t * HH + i] * inv * w[i];
        bf16 h, l; split_bf(v, h, l);
        g_xh[(size_t)t * HH + i] = h; g_xl[(size_t)t * HH + i] = l;
    }
}

// rmsnorm -> fp32 x2 (gating) + fp16 hi/lo (MoE A operand)
__global__ void k_norm(const float* __restrict__ in, const float* __restrict__ w) {
    int t = blockIdx.x;
    __shared__ float red[256];
    float ss = 0.f;
    for (int i = threadIdx.x; i < HH; i += 256) { float v = in[(size_t)t * HH + i]; ss += v * v; }
    red[threadIdx.x] = ss; __syncthreads();
    for (int s = 128; s > 0; s >>= 1) { if (threadIdx.x < s) red[threadIdx.x] += red[threadIdx.x + s]; __syncthreads(); }
    float inv = rsqrtf(red[0] / (float)HH + EPSV);
    __half* xh2 = (__half*)g_x2h;
    __half* xl2 = (__half*)g_x2l;
    for (int i = threadIdx.x; i < HH; i += 256) {
        float v = in[(size_t)t * HH + i] * inv * w[i];
        g_x2[(size_t)t * HH + i] = v;
        __half h, l; split_hf(v, h, l);
        xh2[(size_t)t * HH + i] = h; xl2[(size_t)t * HH + i] = l;
    }
}

// ---------------- RoPE ----------------
__global__ void k_rope(const int* __restrict__ pos, const float* __restrict__ qkv) {
    int t = blockIdx.x;
    float fp = (float)pos[t];
    for (int idx = threadIdx.x; idx < (NH + NKV) * 64; idx += 256) {
        int hh = idx >> 6, d = idx & 63;
        float inv = powf(1e6f, -(float)d / 64.f);
        float ang = fp * inv;
        float c = cosf(ang), s = sinf(ang);
        const float* p = qkv + (size_t)t * QKVD + hh * HD;
        float x1 = p[d], x2 = p[d + 64];
        float v1 = x1 * c - x2 * s;
        float v2 = x2 * c + x1 * s;
        bf16 h1, l1, h2, l2;
        split_bf(v1, h1, l1); split_bf(v2, h2, l2);
        if (hh < NH) {
            size_t b = (size_t)t * (NH * HD) + hh * HD;
            g_qh[b + d] = h1; g_ql[b + d] = l1;
            g_qh[b + d + 64] = h2; g_ql[b + d + 64] = l2;
        } else {
            int kv = hh - NH;
            size_t b = (size_t)kv * TT * HD + (size_t)t * HD;
            g_kbh[b + d] = h1; g_kbl[b + d] = l1;
            g_kbh[b + d + 64] = h2; g_kbl[b + d + 64] = l2;
        }
    }
}

// ---------------- MoE gating ----------------
__global__ void k_gate(const float* __restrict__ x2, const float* __restrict__ gw,
                       const float* __restrict__ gb,
                       int* __restrict__ ids, float* __restrict__ ws) {
    int t = blockIdx.x;
    int tid = threadIdx.x, wid = tid >> 5, lane = tid & 31;
    __shared__ float logit[NE];
    for (int e = wid; e < NE; e += 8) {
        float acc = 0.f;
        for (int i = lane; i < HH; i += 32)
            acc += x2[(size_t)t * HH + i] * gw[(size_t)e * HH + i];
#pragma unroll
        for (int o = 16; o > 0; o >>= 1) acc += __shfl_down_sync(0xffffffffu, acc, o);
        if (lane == 0) logit[e] = acc;
    }
    __syncthreads();
    if (tid == 0) {
        float s[NE], sc[NE];
        for (int e = 0; e < NE; e++) { s[e] = 1.f / (1.f + expf(-logit[e])); sc[e] = s[e] + gb[e]; }
        float gscore[NGRP];
        for (int g = 0; g < NGRP; g++) {
            float a = -3.4e38f, b = -3.4e38f;
            for (int j = 0; j < GSZ; j++) {
                float v = sc[g * GSZ + j];
                if (v > a) { b = a; a = v; } else if (v > b) b = v;
            }
            gscore[g] = a + b;
        }
        bool gsel[NGRP] = {false, false, false, false};
        for (int k = 0; k < TGRP; k++) {
            int best = -1; float bv = -3.4e38f;
            for (int g = 0; g < NGRP; g++)
                if (!gsel[g] && gscore[g] > bv) { bv = gscore[g]; best = g; }
            gsel[best] = true;
        }
        bool used[NE];
        for (int e = 0; e < NE; e++) used[e] = !gsel[e / GSZ];
        float tsum = 0.f;
        int pick[TOPK]; float pw[TOPK];
        for (int k = 0; k < TOPK; k++) {
            int best = -1; float bv = -3.4e38f;
            for (int e = 0; e < NE; e++)
                if (!used[e] && sc[e] > bv) { bv = sc[e]; best = e; }
            used[best] = true;
            pick[k] = best; pw[k] = s[best]; tsum += s[best];
        }
        float inv = 1.f / tsum;
        for (int k = 0; k < TOPK; k++) {
            ids[t * TOPK + k] = pick[k];
            ws[t * TOPK + k] = pw[k] * inv;
        }
    }
}

__global__ void k_scatter(const int* __restrict__ ids, const float* __restrict__ ws) {
    int i = blockIdx.x * 256 + threadIdx.x;
    if (i >= TT * TOPK) return;
    int e = ids[i];
    int slot = atomicAdd(&g_cnt[e], 1);
    g_tok[e * TT + slot] = i / TOPK;
    g_wgt[e * TT + slot] = ws[i];
}

// ---------------- launch ----------------
extern "C" void kernel_launch(void* const* d_in, const int* in_sizes, int n_in,
                              void* d_out_, int out_size) {
    const int*   positions = (const int*)d_in[0];
    const float* hs   = (const float*)d_in[1];
    const float* res  = (const float*)d_in[2];
    const float* wln1 = (const float*)d_in[3];
    const float* wln2 = (const float*)d_in[4];
    const float* wqkv = (const float*)d_in[5];
    const float* wo   = (const float*)d_in[6];
    const float* gw   = (const float*)d_in[7];
    const float* gb   = (const float*)d_in[8];
    const float* wgu  = (const float*)d_in[9];
    const float* wd   = (const float*)d_in[10];
    float* out  = (float*)d_out_;
    float* res2 = out + (size_t)TT * HH;

    void* p;
    float *res1, *qkv, *x2, *wgt;
    bf16 *xh, *xl, *x2h, *x2l, *ath, *atl, *acth, *actl, *vth, *vtl;
    bf16 *wqkvh, *wqkvl, *woh, *wol, *wguh, *wdh;
    int *cnt, *tok, *tkid; float* tkw;
    cudaGetSymbolAddress(&p, g_res1);   res1 = (float*)p;
    cudaGetSymbolAddress(&p, g_qkv);    qkv = (float*)p;
    cudaGetSymbolAddress(&p, g_x2);     x2 = (float*)p;
    cudaGetSymbolAddress(&p, g_xh);  xh = (bf16*)p;  cudaGetSymbolAddress(&p, g_xl);  xl = (bf16*)p;
    cudaGetSymbolAddress(&p, g_x2h); x2h = (bf16*)p; cudaGetSymbolAddress(&p, g_x2l); x2l = (bf16*)p;
    cudaGetSymbolAddress(&p, g_attnh); ath = (bf16*)p; cudaGetSymbolAddress(&p, g_attnl); atl = (bf16*)p;
    cudaGetSymbolAddress(&p, g_acth); acth = (bf16*)p; cudaGetSymbolAddress(&p, g_actl); actl = (bf16*)p;
    cudaGetSymbolAddress(&p, g_vth); vth = (bf16*)p; cudaGetSymbolAddress(&p, g_vtl); vtl = (bf16*)p;
    cudaGetSymbolAddress(&p, g_wqkvh); wqkvh = (bf16*)p; cudaGetSymbolAddress(&p, g_wqkvl); wqkvl = (bf16*)p;
    cudaGetSymbolAddress(&p, g_woh);   woh = (bf16*)p;   cudaGetSymbolAddress(&p, g_wol);   wol = (bf16*)p;
    cudaGetSymbolAddress(&p, g_wguh);  wguh = (bf16*)p;
    cudaGetSymbolAddress(&p, g_wdh);   wdh = (bf16*)p;
    cudaGetSymbolAddress(&p, g_cnt); cnt = (int*)p;
    cudaGetSymbolAddress(&p, g_tok); tok = (int*)p;
    cudaGetSymbolAddress(&p, g_wgt); wgt = (float*)p;
    cudaGetSymbolAddress(&p, g_topk_id); tkid = (int*)p;
    cudaGetSymbolAddress(&p, g_topk_w);  tkw = (float*)p;

    cudaFuncSetAttribute(gemm_m<false, 6, false>, cudaFuncAttributeMaxDynamicSharedMemorySize, GSM);
    cudaFuncSetAttribute(gemm_m<false, 2, false>, cudaFuncAttributeMaxDynamicSharedMemorySize, GSM);
    cudaFuncSetAttribute(gemm_m<true,  5, true>,  cudaFuncAttributeMaxDynamicSharedMemorySize, GSM);
    cudaFuncSetAttribute(gemm_m<false, 7, true>,  cudaFuncAttributeMaxDynamicSharedMemorySize, GSM);
    cudaFuncSetAttribute(k_flash, cudaFuncAttributeMaxDynamicSharedMemorySize, FA_SMEM);

    cudaStream_t s2;
    cudaStreamCreateWithFlags(&s2, cudaStreamNonBlocking);
    cudaEvent_t evFork, evWo, evWgu, evWd;
    cudaEventCreateWithFlags(&evFork, cudaEventDisableTiming);
    cudaEventCreateWithFlags(&evWo,   cudaEventDisableTiming);
    cudaEventCreateWithFlags(&evWgu,  cudaEventDisableTiming);
    cudaEventCreateWithFlags(&evWd,   cudaEventDisableTiming);

    cudaMemsetAsync(qkv, 0, (size_t)TT * QKVD * sizeof(float));
    cudaMemsetAsync(out, 0, (size_t)TT * HH * sizeof(float));
    cudaMemsetAsync(cnt, 0, NE * sizeof(int));

    cudaEventRecord(evFork, 0);
    cudaStreamWaitEvent(s2, evFork, 0);
    { long n = (long)HH * HH;   k_conv<<<(unsigned)((n / 8 + 255) / 256), 256, 0, s2>>>(wo, woh, wol, n); }
    cudaEventRecord(evWo, s2);
    { long n = (long)NE * HH * (IM / 8); k_conv_guh<<<(unsigned)((n + 255) / 256), 256, 0, s2>>>(wgu, wguh); }
    cudaEventRecord(evWgu, s2);
    { long n = (long)NE * IM * HH; k_convh<<<(unsigned)((n / 8 + 255) / 256), 256, 0, s2>>>(wd, wdh, n); }
    cudaEventRecord(evWd, s2);

    // main stream
    { long n = (long)HH * QKVD; k_conv<<<(unsigned)((n / 8 + 255) / 256), 256>>>(wqkv, wqkvh, wqkvl, n); }
    k_addnorm<<<TT, 256>>>(hs, res, wln1, res1);

    // qkv = x @ wqkv  (split-K=3, atomicAdd epilogue, bf16x3)
    { dim3 g(QKVD / BNT, TT / BMT, 3);
      gemm_m<false, 6, false><<<g, 256, GSM>>>(
          xh, xl, HH, 0, wqkvh, wqkvl, QKVD, 0, 1,
          qkv, nullptr, nullptr, QKVD, 0, TT, QKVD, HH,
          nullptr, nullptr, 0, nullptr, 0, 1.f); }

    // rope ; V transpose+convert
    k_rope<<<TT, 256>>>(positions, qkv);
    { dim3 g(HD / 32, TT / 32, NKV);
      k_tconv<<<g, dim3(32, 8)>>>(qkv + (NH + NKV) * HD, QKVD, HD, vth, vtl, TT, (long)HD * TT, TT, HD); }

    // flash attention
    { dim3 g(NH, TT / 128); k_flash<<<g, 256, FA_SMEM>>>(); }

    // res2 = attn @ wo + res1 (bf16x3)
    cudaStreamWaitEvent(0, evWo, 0);
    { dim3 g(HH / BNT, TT / BMT, 1);
      gemm_m<false, 2, false><<<g, 256, GSM>>>(
          ath, atl, HH, 0, woh, wol, HH, 0, 1,
          res2, nullptr, nullptr, HH, 0, TT, HH, HH,
          nullptr, nullptr, 0, res1, 0, 1.f); }

    // x2 = rmsnorm(res2) -> fp32 + fp16 hi/lo
    k_norm<<<TT, 256>>>(res2, wln2);

    // gating + scatter (pure fp32 inputs — decisions unchanged)
    k_gate<<<TT, 256>>>(x2, gw, gb, tkid, tkw);
    k_scatter<<<(TT * TOPK + 255) / 256, 256>>>(tkid, tkw);

    // per-expert gate_up + fused silu (fp16 2-term)
    cudaStreamWaitEvent(0, evWgu, 0);
    { dim3 g((2 * IM) / BNT, TT / BMT, NE);
      gemm_m<true, 5, true><<<g, 256, GSM>>>(
          x2h, x2l, HH, 0, wguh, nullptr, 2 * IM, (long)HH * 2 * IM, 1,
          nullptr, acth, actl, IM, (long)TT * IM, TT, 2 * IM, HH,
          cnt, tok, TT, nullptr, 0, 1.f); }

    // per-expert down + weighted scatter-add (split-K=2, fp16 2-term)
    cudaStreamWaitEvent(0, evWd, 0);
    { dim3 g(HH / BNT, TT / BMT, NE * 2);
      gemm_m<false, 7, true><<<g, 256, GSM>>>(
          acth, actl, IM, (long)TT * IM, wdh, nullptr, HH, (long)IM * HH, 1,
          out, nullptr, nullptr, HH, 0, TT, HH, IM,
          cnt, tok, TT, wgt, TT, 1.f); }

    cudaEventDestroy(evFork);
    cudaEventDestroy(evWo);
    cudaEventDestroy(evWgu);
    cudaEventDestroy(evWd);
    cudaStreamDestroy(s2);
}

// round 15
// speedup vs baseline: 1.2785x; 1.0623x over previous
#include <cuda_runtime.h>
#include <cuda_bf16.h>
#include <cuda_fp16.h>
#include <math.h>
#include <stdint.h>

#define TT 2048
#define HH 2048
#define NH 16
#define NKV 4
#define HD 128
#define NE 16
#define TOPK 4
#define NGRP 4
#define GSZ 4
#define TGRP 2
#define IM 1024
#define QKVD 3072
#define ATT_SCALE 0.08838834764831845f
#define EPSV 1e-6f

typedef __nv_bfloat16 bf16;

// ---------------- scratch (device globals; no allocations) ----------------
__device__ float g_res1[(size_t)TT * HH];
__device__ float g_qkv[(size_t)TT * QKVD];
__device__ float g_x2[(size_t)TT * HH];
__device__ bf16  g_xh[(size_t)TT * HH],  g_xl[(size_t)TT * HH];
__device__ bf16  g_x2h[(size_t)TT * HH], g_x2l[(size_t)TT * HH];      // fp16 bits
__device__ bf16  g_qh[(size_t)TT * (NH * HD)], g_ql[(size_t)TT * (NH * HD)];
__device__ bf16  g_attnh[(size_t)TT * HH], g_attnl[(size_t)TT * HH];
__device__ bf16  g_acth[(size_t)NE * TT * IM];                        // fp16 bits (single)
__device__ bf16  g_kbh[(size_t)NKV * TT * HD], g_kbl[(size_t)NKV * TT * HD];
__device__ bf16  g_vth[(size_t)NKV * HD * TT], g_vtl[(size_t)NKV * HD * TT];
__device__ bf16  g_wqkvh[(size_t)HH * QKVD], g_wqkvl[(size_t)HH * QKVD];
__device__ bf16  g_woh[(size_t)HH * HH],     g_wol[(size_t)HH * HH];
__device__ bf16  g_wguh[(size_t)NE * HH * 2 * IM];                    // fp16 bits (single)
__device__ bf16  g_wdh[(size_t)NE * IM * HH];                         // fp16 bits (single)
__device__ int   g_cnt[NE];
__device__ int   g_tok[NE * TT];
__device__ float g_wgt[NE * TT];
__device__ int   g_topk_id[TT * TOPK];
__device__ float g_topk_w[TT * TOPK];

// ---------------- helpers ----------------
__device__ __forceinline__ uint32_t smem_u32(const void* p) {
    uint32_t a;
    asm("{ .reg .u64 t; cvta.to.shared.u64 t, %1; cvt.u32.u64 %0, t; }" : "=r"(a) : "l"(p));
    return a;
}
__device__ __forceinline__ void split_bf(float v, bf16& h, bf16& l) {
    h = __float2bfloat16_rn(v);
    l = __float2bfloat16_rn(v - __bfloat162float(h));
}
__device__ __forceinline__ void split_hf(float v, __half& h, __half& l) {
    h = __float2half_rn(v);
    l = __float2half_rn(v - __half2float(h));
}
__device__ __forceinline__ uint32_t pack2(bf16 a, bf16 b) {
    return (uint32_t)__bfloat16_as_ushort(a) | ((uint32_t)__bfloat16_as_ushort(b) << 16);
}
__device__ __forceinline__ uint32_t pack2h(__half a, __half b) {
    return (uint32_t)__half_as_ushort(a) | ((uint32_t)__half_as_ushort(b) << 16);
}
__device__ __forceinline__ void cpa(uint32_t d, const void* s, int sz) {
    asm volatile("cp.async.cg.shared.global [%0], [%1], 16, %2;" :: "r"(d), "l"(s), "r"(sz));
}
__device__ __forceinline__ void cpcommit() { asm volatile("cp.async.commit_group;" ::: "memory"); }
__device__ __forceinline__ void cpwaitN(int n) {
    if (n == 0)      asm volatile("cp.async.wait_group 0;" ::: "memory");
    else if (n == 1) asm volatile("cp.async.wait_group 1;" ::: "memory");
    else             asm volatile("cp.async.wait_group 2;" ::: "memory");
}
__device__ __forceinline__ void ldm4(uint32_t* r, uint32_t a) {
    asm volatile("ldmatrix.sync.aligned.m8n8.x4.shared.b16 {%0,%1,%2,%3}, [%4];"
                 : "=r"(r[0]), "=r"(r[1]), "=r"(r[2]), "=r"(r[3]) : "r"(a));
}
__device__ __forceinline__ void ldm4t(uint32_t* r, uint32_t a) {
    asm volatile("ldmatrix.sync.aligned.m8n8.x4.trans.shared.b16 {%0,%1,%2,%3}, [%4];"
                 : "=r"(r[0]), "=r"(r[1]), "=r"(r[2]), "=r"(r[3]) : "r"(a));
}
// non-volatile — lets ptxas schedule MMAs for ILP.
__device__ __forceinline__ void mma16816(float* c, const uint32_t* a, const uint32_t* b) {
    asm("mma.sync.aligned.m16n8k16.row.col.f32.bf16.bf16.f32 "
        "{%0,%1,%2,%3},{%4,%5,%6,%7},{%8,%9},{%0,%1,%2,%3};"
        : "+f"(c[0]), "+f"(c[1]), "+f"(c[2]), "+f"(c[3])
        : "r"(a[0]), "r"(a[1]), "r"(a[2]), "r"(a[3]), "r"(b[0]), "r"(b[1]));
}
__device__ __forceinline__ void mma16816h(float* c, const uint32_t* a, const uint32_t* b) {
    asm("mma.sync.aligned.m16n8k16.row.col.f32.f16.f16.f32 "
        "{%0,%1,%2,%3},{%4,%5,%6,%7},{%8,%9},{%0,%1,%2,%3};"
        : "+f"(c[0]), "+f"(c[1]), "+f"(c[2]), "+f"(c[3])
        : "r"(a[0]), "r"(a[1]), "r"(a[2]), "r"(a[3]), "r"(b[0]), "r"(b[1]));
}

// ---------------- mma.sync GEMM (B K-major, 3-stage, ILP-ordered MMAs) ------------
// TERMS: 3 = bf16x3 (A hi/lo x B hi/lo), 2 = fp16 A hi/lo x single fp16 B,
//        1 = single fp16 A x single fp16 B (MoE down — deepest downstream).
// EPI: 0 fp32 store, 2 add X, 3 atomicAdd scatter, 5 silu(even)*odd -> fp16 single,
//      6 split-K (z = slice, batch 0), 7 split-K x2 + scatter (z = expert*2+slice).
#define BMT 128
#define BNT 128
#define BKT 32
#define AST 80u
#define BST 272u
#define A_SZ 10240u
#define B_SZ 8704u
#define STG2 (2u * A_SZ + 2u * B_SZ)   // 37888
#define NSTG 3
#define GSM (NSTG * 37888)             // 113664

template <bool GA, int EPI, int TERMS>
__global__ void __launch_bounds__(256, 2)
gemm_m(const bf16* __restrict__ Ah0, const bf16* __restrict__ Al0, int lda, long saz,
       const bf16* __restrict__ Bh0, const bf16* __restrict__ Bl0, int ldb, long sbz, int bdiv,
       float* __restrict__ C0, bf16* __restrict__ Oh0, int ldc, long scz,
       int M0, int N, int K,
       const int* __restrict__ Mptr, const int* __restrict__ gidx0, int sgz,
       const float* __restrict__ X0, long sxz, float alpha) {
    int z = blockIdx.z;
    int zb = z, ksl = 0, kns = 1;
    if (EPI == 6) { zb = 0; ksl = z; kns = (int)gridDim.z; }
    if (EPI == 7) { zb = z >> 1; ksl = z & 1; kns = 2; }
    int M = Mptr ? Mptr[zb] : M0;
    int row0 = blockIdx.y * BMT, col0 = blockIdx.x * BNT;
    if (row0 >= M) return;

    extern __shared__ char smem[];
    uint32_t sb = smem_u32(smem);
    int tid = threadIdx.x, lane = tid & 31, wid = tid >> 5;
    const int m0w = (wid & 3) * 32, n0w = (wid >> 2) * 64;

    const int* gidxz = (GA || EPI == 3 || EPI == 7) ? gidx0 + (long)zb * sgz : nullptr;
    const float* X = (EPI == 2 || EPI == 3 || EPI == 7) ? X0 + (long)zb * sxz : nullptr;
    const bf16* Bh = Bh0 + (long)(zb / bdiv) * sbz + col0;
    const bf16* Bl = (TERMS == 3) ? (Bl0 + (long)(zb / bdiv) * sbz + col0) : nullptr;

    int nchTot = K / BKT;
    int c0 = (nchTot * ksl) / kns;
    int c1 = (nchTot * (ksl + 1)) / kns;

    int lrow = tid >> 1, lhalf = tid & 1;
    int ari = row0 + lrow;
    bool av = ari < M;
    long agrow = ari;
    if (GA) agrow = av ? (long)gidxz[ari] : 0;
    long arow2 = (GA ? agrow : (long)ari);
    const bf16* agh2 = Ah0 + (long)zb * saz + arow2 * (long)lda;
    const bf16* agl2 = (TERMS >= 2) ? (Al0 + (long)zb * saz + arow2 * (long)lda) : nullptr;
    int asz = av ? 16 : 0;
    uint32_t dst_a = sb + lrow * AST + lhalf * 32;
    int brow = tid >> 3, bth = tid & 7;
    uint32_t dst_b = sb + 2 * A_SZ + brow * BST + bth * 32;

    auto cp_stage = [&](int buf, int k0) {
        uint32_t so = buf * STG2;
        long ko = k0 + lhalf * 16;
        cpa(dst_a + so,             agh2 + ko,     asz);
        cpa(dst_a + so + 16,        agh2 + ko + 8, asz);
        if (TERMS >= 2) {
            cpa(dst_a + so + A_SZ,      agl2 + ko,     asz);
            cpa(dst_a + so + A_SZ + 16, agl2 + ko + 8, asz);
        }
        long bko = (long)(k0 + brow) * ldb + bth * 16;
        cpa(dst_b + so,             Bh + bko,     16);
        cpa(dst_b + so + 16,        Bh + bko + 8, 16);
        if (TERMS == 3) {
            cpa(dst_b + so + B_SZ,      Bl + bko,     16);
            cpa(dst_b + so + B_SZ + 16, Bl + bko + 8, 16);
        }
    };

    float acc[2][8][4];
#pragma unroll
    for (int i = 0; i < 2; i++)
#pragma unroll
        for (int j = 0; j < 8; j++)
#pragma unroll
            for (int q = 0; q < 4; q++) acc[i][j][q] = 0.f;

    uint32_t a_off = (uint32_t)(m0w + (lane & 15)) * AST + (uint32_t)(lane >> 4) * 16;
    uint32_t b_off = (uint32_t)((lane & 7) + ((lane >> 3) & 1) * 8) * BST
                   + (uint32_t)(lane >> 4) * 16;

    auto compute = [&](int buf) {
        uint32_t ab  = sb + buf * STG2;
        uint32_t alb = ab + A_SZ;
        uint32_t bhb = ab + 2 * A_SZ;
        uint32_t blb = bhb + B_SZ;
#pragma unroll
        for (int s = 0; s < 2; s++) {
            uint32_t ka = s * 32;
            uint32_t ah0[4], ah1[4], al0[4], al1[4];
            ldm4(ah0, ab + a_off + ka);
            ldm4(ah1, ab + a_off + 16 * AST + ka);
            if (TERMS >= 2) {
                ldm4(al0, alb + a_off + ka);
                ldm4(al1, alb + a_off + 16 * AST + ka);
            }
            uint32_t bs = b_off + s * (16 * BST);
#pragma unroll
            for (int np = 0; np < 4; np++) {
                uint32_t bo = bs + (uint32_t)((n0w + np * 16) * 2);
                int ne = 2 * np, no = 2 * np + 1;
                if (TERMS == 1) {
                    uint32_t bh[4];
                    ldm4t(bh, bhb + bo);
                    mma16816h(acc[0][ne], ah0, bh);  mma16816h(acc[0][no], ah0, bh + 2);
                    mma16816h(acc[1][ne], ah1, bh);  mma16816h(acc[1][no], ah1, bh + 2);
                } else if (TERMS == 2) {
                    uint32_t bh[4];
                    ldm4t(bh, bhb + bo);
                    mma16816h(acc[0][ne], ah0, bh);  mma16816h(acc[0][no], ah0, bh + 2);
                    mma16816h(acc[1][ne], ah1, bh);  mma16816h(acc[1][no], ah1, bh + 2);
                    mma16816h(acc[0][ne], al0, bh);  mma16816h(acc[0][no], al0, bh + 2);
                    mma16816h(acc[1][ne], al1, bh);  mma16816h(acc[1][no], al1, bh + 2);
                } else {
                    uint32_t bh[4], bl[4];
                    ldm4t(bh, bhb + bo);
                    ldm4t(bl, blb + bo);
                    mma16816(acc[0][ne], ah0, bh);     mma16816(acc[0][no], ah0, bh + 2);
                    mma16816(acc[1][ne], ah1, bh);     mma16816(acc[1][no], ah1, bh + 2);
                    mma16816(acc[0][ne], ah0, bl);     mma16816(acc[0][no], ah0, bl + 2);
                    mma16816(acc[1][ne], ah1, bl);     mma16816(acc[1][no], ah1, bl + 2);
                    mma16816(acc[0][ne], al0, bh);     mma16816(acc[0][no], al0, bh + 2);
                    mma16816(acc[1][ne], al1, bh);     mma16816(acc[1][no], al1, bh + 2);
                }
            }
        }
    };

    cp_stage(0, c0 * BKT); cpcommit();
    cp_stage(1, (c0 + 1) * BKT); cpcommit();
    int buf = 0;
    for (int c = c0; c < c1; c++) {
        cpwaitN(1);
        __syncthreads();
        compute(buf);
        int nb = buf + 1; if (nb == NSTG) nb = 0;
        int pb = buf + 2; if (pb >= NSTG) pb -= NSTG;
        if (c + 2 < c1) cp_stage(pb, (c + 2) * BKT);
        cpcommit();
        buf = nb;
    }

    // epilogue
    int lq = lane >> 2, lr = lane & 3;
#pragma unroll
    for (int mt = 0; mt < 2; mt++) {
        int r0 = row0 + m0w + mt * 16 + lq;
        int r1 = r0 + 8;
#pragma unroll
        for (int nt = 0; nt < 8; nt++) {
            long cc = (long)col0 + n0w + nt * 8 + 2 * lr;
            float v0 = acc[mt][nt][0] * alpha, v1 = acc[mt][nt][1] * alpha;
            float v2 = acc[mt][nt][2] * alpha, v3 = acc[mt][nt][3] * alpha;
            if (EPI == 6) {
                float* C = C0;
                if (r0 < M) {
                    atomicAdd(&C[(long)r0 * ldc + cc], v0);
                    atomicAdd(&C[(long)r0 * ldc + cc + 1], v1);
                }
                if (r1 < M) {
                    atomicAdd(&C[(long)r1 * ldc + cc], v2);
                    atomicAdd(&C[(long)r1 * ldc + cc + 1], v3);
                }
            } else if (EPI == 3 || EPI == 7) {
                float* C = C0 + (EPI == 3 ? (long)zb * scz : 0);
                if (r0 < M) {
                    long gr = gidxz[r0]; float w = X[r0];
                    atomicAdd(&C[gr * ldc + cc], w * v0);
                    atomicAdd(&C[gr * ldc + cc + 1], w * v1);
                }
                if (r1 < M) {
                    long gr = gidxz[r1]; float w = X[r1];
                    atomicAdd(&C[gr * ldc + cc], w * v2);
                    atomicAdd(&C[gr * ldc + cc + 1], w * v3);
                }
            } else if (EPI == 5) {
                __half* oh = (__half*)(Oh0 + (long)zb * scz);
                long co = cc >> 1;
                if (r0 < M) {
                    float a = v0 / (1.f + expf(-v0)) * v1;
                    oh[(long)r0 * ldc + co] = __float2half_rn(a);
                }
                if (r1 < M) {
                    float a = v2 / (1.f + expf(-v2)) * v3;
                    oh[(long)r1 * ldc + co] = __float2half_rn(a);
                }
            } else if (EPI == 2) {
                float* C = C0 + (long)zb * scz;
                if (r0 < M) {
                    float2 xv = *(const float2*)&X[(long)r0 * ldc + cc];
                    *(float2*)&C[(long)r0 * ldc + cc] = make_float2(v0 + xv.x, v1 + xv.y);
                }
                if (r1 < M) {
                    float2 xv = *(const float2*)&X[(long)r1 * ldc + cc];
                    *(float2*)&C[(long)r1 * ldc + cc] = make_float2(v2 + xv.x, v3 + xv.y);
                }
            } else {
                float* C = C0 + (long)zb * scz;
                if (r0 < M) *(float2*)&C[(long)r0 * ldc + cc] = make_float2(v0, v1);
                if (r1 < M) *(float2*)&C[(long)r1 * ldc + cc] = make_float2(v2, v3);
            }
        }
    }
}

// ---------------- flash attention (bf16x3, online softmax) ----------------
#define FA_Q  0u
#define FA_QL 40960u
#define FA_K  81920u
#define FA_KL 122880u
#define FA_V  163840u
#define FA_VL 184320u
#define FA_SMEM 204800

__global__ void __launch_bounds__(256, 1) k_flash() {
    extern __shared__ char smem[];
    uint32_t sb = smem_u32(smem);
    int head = blockIdx.x;
    int qb = (int)gridDim.y - 1 - (int)blockIdx.y;
    int row0 = qb * 128;
    int kv = head >> 2;
    int tid = threadIdx.x, lane = tid & 31, w = tid >> 5;
    int lq = lane >> 2, lr = lane & 3;
    int lrow = tid >> 1, lhalf = tid & 1;

    const bf16* qgh = g_qh + (size_t)(row0 + lrow) * (NH * HD) + head * HD + lhalf * 16;
    const bf16* qgl = g_ql + (size_t)(row0 + lrow) * (NH * HD) + head * HD + lhalf * 16;
    const bf16* kgh = g_kbh + (size_t)kv * TT * HD + (size_t)lrow * HD + lhalf * 16;
    const bf16* kgl = g_kbl + (size_t)kv * TT * HD + (size_t)lrow * HD + lhalf * 16;
    const bf16* vgh = g_vth + (size_t)kv * HD * TT + (size_t)lrow * TT + lhalf * 16;
    const bf16* vgl = g_vtl + (size_t)kv * HD * TT + (size_t)lrow * TT + lhalf * 16;

#pragma unroll
    for (int c = 0; c < 4; c++) {
        uint32_t d = sb + FA_Q + (uint32_t)((c * 128 + lrow) * 80) + lhalf * 32;
        cpa(d, qgh + c * 32, 16); cpa(d + 16, qgh + c * 32 + 8, 16);
        uint32_t dl = d + (FA_QL - FA_Q);
        cpa(dl, qgl + c * 32, 16); cpa(dl + 16, qgl + c * 32 + 8, 16);
    }
    cpcommit();

    auto issueK = [&](int s0) {
#pragma unroll
        for (int c = 0; c < 4; c++) {
            uint32_t d = sb + FA_K + (uint32_t)((c * 128 + lrow) * 80) + lhalf * 32;
            const bf16* s = kgh + (size_t)s0 * HD + c * 32;
            cpa(d, s, 16); cpa(d + 16, s + 8, 16);
            uint32_t dl = d + (FA_KL - FA_K);
            const bf16* sl = kgl + (size_t)s0 * HD + c * 32;
            cpa(dl, sl, 16); cpa(dl + 16, sl + 8, 16);
        }
        cpcommit();
    };
    auto issueV = [&](int s0, int c) {
        uint32_t d = sb + FA_V + (uint32_t)(((c & 1) * 128 + lrow) * 80) + lhalf * 32;
        const bf16* s = vgh + s0 + c * 32;
        cpa(d, s, 16); cpa(d + 16, s + 8, 16);
        uint32_t dl = d + (FA_VL - FA_V);
        const bf16* sl = vgl + s0 + c * 32;
        cpa(dl, sl, 16); cpa(dl + 16, sl + 8, 16);
        cpcommit();
    };
    issueK(0);

    float O[16][4];
#pragma unroll
    for (int i = 0; i < 16; i++) { O[i][0] = O[i][1] = O[i][2] = O[i][3] = 0.f; }
    float m_lo = -1e30f, m_hi = -1e30f, l_lo = 0.f, l_hi = 0.f;
    int ntl = qb + 1;
    uint32_t a_off = (uint32_t)((w * 16 + (lane & 15)) * 80) + (uint32_t)(lane >> 4) * 16;
    uint32_t b_off = (uint32_t)((((lane >> 4) << 3) + (lane & 7)) * 80) + (uint32_t)((lane >> 3) & 1) * 16;

    for (int st = 0; st < ntl; st++) {
        int s0 = st * 128;
        __syncthreads();
        issueV(s0, 0); issueV(s0, 1);
        asm volatile("cp.async.wait_group 2;" ::: "memory");
        __syncthreads();

        float S[16][4];
#pragma unroll
        for (int i = 0; i < 16; i++) { S[i][0] = S[i][1] = S[i][2] = S[i][3] = 0.f; }
#pragma unroll
        for (int kc = 0; kc < 4; kc++)
#pragma unroll
        for (int ks = 0; ks < 2; ks++) {
            uint32_t qa = sb + (uint32_t)(kc * 128 * 80) + a_off + ks * 32;
            uint32_t ah[4], al[4];
            ldm4(ah, qa + FA_Q);
            ldm4(al, qa + FA_QL);
#pragma unroll
            for (int j = 0; j < 8; j++) {
                uint32_t kb = sb + FA_K + (uint32_t)((kc * 128 + 16 * j) * 80) + b_off + ks * 32;
                uint32_t bh[4], bl[4];
                ldm4(bh, kb); ldm4(bl, kb + (FA_KL - FA_K));
                mma16816(S[2 * j],     ah, bh);     mma16816(S[2 * j + 1], ah, bh + 2);
                mma16816(S[2 * j],     ah, bl);     mma16816(S[2 * j + 1], ah, bl + 2);
                mma16816(S[2 * j],     al, bh);     mma16816(S[2 * j + 1], al, bh + 2);
            }
        }

        bool dg = (st == qb);
        int rlo = row0 + w * 16 + lq, rhi = rlo + 8;
#pragma unroll
        for (int nt = 0; nt < 16; nt++) {
            int cbase = s0 + nt * 8 + 2 * lr;
#pragma unroll
            for (int q = 0; q < 4; q++) {
                float v = S[nt][q] * ATT_SCALE;
                int col = cbase + (q & 1);
                int rw = (q < 2) ? rlo : rhi;
                if (dg && col > rw) v = -1e30f;
                S[nt][q] = v;
            }
        }
        float mx0 = -1e30f, mx1 = -1e30f;
#pragma unroll
        for (int nt = 0; nt < 16; nt++) {
            mx0 = fmaxf(mx0, fmaxf(S[nt][0], S[nt][1]));
            mx1 = fmaxf(mx1, fmaxf(S[nt][2], S[nt][3]));
        }
        mx0 = fmaxf(mx0, __shfl_xor_sync(0xffffffffu, mx0, 1));
        mx0 = fmaxf(mx0, __shfl_xor_sync(0xffffffffu, mx0, 2));
        mx1 = fmaxf(mx1, __shfl_xor_sync(0xffffffffu, mx1, 1));
        mx1 = fmaxf(mx1, __shfl_xor_sync(0xffffffffu, mx1, 2));
        float mn0 = fmaxf(m_lo, mx0), mn1 = fmaxf(m_hi, mx1);
        float sc0 = expf(m_lo - mn0), sc1 = expf(m_hi - mn1);
        float rs0 = 0.f, rs1 = 0.f;
#pragma unroll
        for (int nt = 0; nt < 16; nt++) {
            S[nt][0] = expf(S[nt][0] - mn0); S[nt][1] = expf(S[nt][1] - mn0);
            S[nt][2] = expf(S[nt][2] - mn1); S[nt][3] = expf(S[nt][3] - mn1);
            rs0 += S[nt][0] + S[nt][1];
            rs1 += S[nt][2] + S[nt][3];
        }
        rs0 += __shfl_xor_sync(0xffffffffu, rs0, 1); rs0 += __shfl_xor_sync(0xffffffffu, rs0, 2);
        rs1 += __shfl_xor_sync(0xffffffffu, rs1, 1); rs1 += __shfl_xor_sync(0xffffffffu, rs1, 2);
        l_lo = l_lo * sc0 + rs0; l_hi = l_hi * sc1 + rs1;
        m_lo = mn0; m_hi = mn1;
#pragma unroll
        for (int nt = 0; nt < 16; nt++) {
            O[nt][0] *= sc0; O[nt][1] *= sc0; O[nt][2] *= sc1; O[nt][3] *= sc1;
        }

        __syncthreads();
        bool haveK = (st + 1 < ntl);
        if (haveK) issueK(s0 + 128);

#pragma unroll 1
        for (int c = 0; c < 4; c++) {
            int pend = haveK ? (c <= 1 ? 2 : (c == 2 ? 1 : 0)) : (c < 3 ? 1 : 0);
            cpwaitN(pend);
            __syncthreads();
#pragma unroll
            for (int ks = 0; ks < 2; ks++) {
                int t0 = 2 * (2 * c + ks), t1 = t0 + 1;
                uint32_t pah[4], pal[4];
                bf16 h0, l0, h1, l1;
                split_bf(S[t0][0], h0, l0); split_bf(S[t0][1], h1, l1);
                pah[0] = pack2(h0, h1); pal[0] = pack2(l0, l1);
                split_bf(S[t0][2], h0, l0); split_bf(S[t0][3], h1, l1);
                pah[1] = pack2(h0, h1); pal[1] = pack2(l0, l1);
                split_bf(S[t1][0], h0, l0); split_bf(S[t1][1], h1, l1);
                pah[2] = pack2(h0, h1); pal[2] = pack2(l0, l1);
                split_bf(S[t1][2], h0, l0); split_bf(S[t1][3], h1, l1);
                pah[3] = pack2(h0, h1); pal[3] = pack2(l0, l1);
#pragma unroll
                for (int j = 0; j < 8; j++) {
                    uint32_t vb = sb + FA_V + (uint32_t)((((c & 1) * 128) + 16 * j) * 80) + b_off + ks * 32;
                    uint32_t vh[4], vl[4];
                    ldm4(vh, vb); ldm4(vl, vb + (FA_VL - FA_V));
                    mma16816(O[2 * j],     pah, vh);     mma16816(O[2 * j + 1], pah, vh + 2);
                    mma16816(O[2 * j],     pah, vl);     mma16816(O[2 * j + 1], pah, vl + 2);
                    mma16816(O[2 * j],     pal, vh);     mma16816(O[2 * j + 1], pal, vh + 2);
                }
            }
            __syncthreads();
            if (c + 2 < 4) issueV(s0, c + 2);
        }
    }

    float il0 = 1.f / l_lo, il1 = 1.f / l_hi;
    int rlo = row0 + w * 16 + lq, rhi = rlo + 8;
#pragma unroll
    for (int nt = 0; nt < 16; nt++) {
        long col = (long)head * HD + nt * 8 + 2 * lr;
        bf16 h0, l0, h1, l1;
        float v0 = O[nt][0] * il0, v1 = O[nt][1] * il0;
        split_bf(v0, h0, l0); split_bf(v1, h1, l1);
        *(uint32_t*)&g_attnh[(long)rlo * HH + col] = pack2(h0, h1);
        *(uint32_t*)&g_attnl[(long)rlo * HH + col] = pack2(l0, l1);
        float v2 = O[nt][2] * il1, v3 = O[nt][3] * il1;
        split_bf(v2, h0, l0); split_bf(v3, h1, l1);
        *(uint32_t*)&g_attnh[(long)rhi * HH + col] = pack2(h0, h1);
        *(uint32_t*)&g_attnl[(long)rhi * HH + col] = pack2(l0, l1);
    }
}

// ---------------- streaming convert fp32 -> bf16 hi/lo (8 elems/thread) -----------
__global__ void k_conv(const float* __restrict__ in, bf16* __restrict__ oh,
                       bf16* __restrict__ ol, long n) {
    long i = ((long)blockIdx.x * 256 + threadIdx.x) * 8;
    if (i >= n) return;
    float4 a = *(const float4*)(in + i);
    float4 b = *(const float4*)(in + i + 4);
    bf16 h0, l0, h1, l1;
    uint32_t H[4], L[4];
    split_bf(a.x, h0, l0); split_bf(a.y, h1, l1); H[0] = pack2(h0, h1); L[0] = pack2(l0, l1);
    split_bf(a.z, h0, l0); split_bf(a.w, h1, l1); H[1] = pack2(h0, h1); L[1] = pack2(l0, l1);
    split_bf(b.x, h0, l0); split_bf(b.y, h1, l1); H[2] = pack2(h0, h1); L[2] = pack2(l0, l1);
    split_bf(b.z, h0, l0); split_bf(b.w, h1, l1); H[3] = pack2(h0, h1); L[3] = pack2(l0, l1);
    *(uint4*)(oh + i) = make_uint4(H[0], H[1], H[2], H[3]);
    *(uint4*)(ol + i) = make_uint4(L[0], L[1], L[2], L[3]);
}

// fp32 -> single fp16 (8 elems/thread) for wd
__global__ void k_convh(const float* __restrict__ in, bf16* __restrict__ oh, long n) {
    long i = ((long)blockIdx.x * 256 + threadIdx.x) * 8;
    if (i >= n) return;
    float4 a = *(const float4*)(in + i);
    float4 b = *(const float4*)(in + i + 4);
    uint32_t H[4];
    H[0] = pack2h(__float2half_rn(a.x), __float2half_rn(a.y));
    H[1] = pack2h(__float2half_rn(a.z), __float2half_rn(a.w));
    H[2] = pack2h(__float2half_rn(b.x), __float2half_rn(b.y));
    H[3] = pack2h(__float2half_rn(b.z), __float2half_rn(b.w));
    *(uint4*)(oh + i) = make_uint4(H[0], H[1], H[2], H[3]);
}

// gate/up column interleave, single fp16 (8 gate + 8 up per thread)
__global__ void k_conv_guh(const float* __restrict__ in, bf16* __restrict__ oh) {
    long t = (long)blockIdx.x * 256 + threadIdx.x;
    long rows = (long)NE * HH;
    long perRow = IM / 8;
    if (t >= rows * perRow) return;
    long row = t / perRow;
    long c = (t % perRow) * 8;
    const float* base = in + row * (2 * IM);
    float4 gA = *(const float4*)(base + c);
    float4 gB = *(const float4*)(base + c + 4);
    float4 uA = *(const float4*)(base + IM + c);
    float4 uB = *(const float4*)(base + IM + c + 4);
    uint32_t H[8];
    H[0] = pack2h(__float2half_rn(gA.x), __float2half_rn(uA.x));
    H[1] = pack2h(__float2half_rn(gA.y), __float2half_rn(uA.y));
    H[2] = pack2h(__float2half_rn(gA.z), __float2half_rn(uA.z));
    H[3] = pack2h(__float2half_rn(gA.w), __float2half_rn(uA.w));
    H[4] = pack2h(__float2half_rn(gB.x), __float2half_rn(uB.x));
    H[5] = pack2h(__float2half_rn(gB.y), __float2half_rn(uB.y));
    H[6] = pack2h(__float2half_rn(gB.z), __float2half_rn(uB.z));
    H[7] = pack2h(__float2half_rn(gB.w), __float2half_rn(uB.w));
    bf16* po = oh + row * (2 * IM) + 2 * c;
    *(uint4*)po       = make_uint4(H[0], H[1], H[2], H[3]);
    *(uint4*)(po + 8) = make_uint4(H[4], H[5], H[6], H[7]);
}

// ---------------- transpose + convert (V only) ----------------
__global__ void k_tconv(const float* __restrict__ in, long ldin, long sbin,
                        bf16* __restrict__ oh, bf16* __restrict__ ol, long ldo, long sbo,
                        int R, int C) {
    __shared__ float t[32][33];
    int z = blockIdx.z;
    const float* I = in + (long)z * sbin;
    int c0 = blockIdx.x * 32, r0 = blockIdx.y * 32;
#pragma unroll
    for (int i = 0; i < 4; i++) {
        int r = r0 + threadIdx.y + i * 8, c = c0 + threadIdx.x;
        t[threadIdx.y + i * 8][threadIdx.x] = (r < R && c < C) ? I[(long)r * ldin + c] : 0.f;
    }
    __syncthreads();
#pragma unroll
    for (int i = 0; i < 4; i++) {
        int orow = c0 + threadIdx.y + i * 8, ocol = r0 + threadIdx.x;
        if (orow < C && ocol < R) {
            bf16 h, l;
            split_bf(t[threadIdx.x][threadIdx.y + i * 8], h, l);
            oh[(long)z * sbo + (long)orow * ldo + ocol] = h;
            ol[(long)z * sbo + (long)orow * ldo + ocol] = l;
        }
    }
}

// ---------------- residual add + rmsnorm ----------------
__global__ void k_addnorm(const float* __restrict__ hs, const float* __restrict__ res,
                          const float* __restrict__ w, float* __restrict__ res_out) {
    int t = blockIdx.x;
    __shared__ float red[256];
    float ss = 0.f;
    for (int i = threadIdx.x; i < HH; i += 256) {
        float v = hs[(size_t)t * HH + i] + res[(size_t)t * HH + i];
        res_out[(size_t)t * HH + i] = v;
        ss += v * v;
    }
    red[threadIdx.x] = ss; __syncthreads();
    for (int s = 128; s > 0; s >>= 1) { if (threadIdx.x < s) red[threadIdx.x] += red[threadIdx.x + s]; __syncthreads(); }
    float inv = rsqrtf(red[0] / (float)HH + EPSV);
    for (int i = threadIdx.x; i < HH; i += 256) {
        float v = res_out[(size_t)t * HH + i] * inv * w[i];
        bf16 h, l; split_bf(v, h, l);
        g_xh[(size_t)t * HH + i] = h; g_xl[(size_t)t * HH + i] = l;
    }
}

// rmsnorm -> fp32 x2 (gating) + fp16 hi/lo (MoE A operand)
__global__ void k_norm(const float* __restrict__ in, const float* __restrict__ w) {
    int t = blockIdx.x;
    __shared__ float red[256];
    float ss = 0.f;
    for (int i = threadIdx.x; i < HH; i += 256) { float v = in[(size_t)t * HH + i]; ss += v * v; }
    red[threadIdx.x] = ss; __syncthreads();
    for (int s = 128; s > 0; s >>= 1) { if (threadIdx.x < s) red[threadIdx.x] += red[threadIdx.x + s]; __syncthreads(); }
    float inv = rsqrtf(red[0] / (float)HH + EPSV);
    __half* xh2 = (__half*)g_x2h;
    __half* xl2 = (__half*)g_x2l;
    for (int i = threadIdx.x; i < HH; i += 256) {
        float v = in[(size_t)t * HH + i] * inv * w[i];
        g_x2[(size_t)t * HH + i] = v;
        __half h, l; split_hf(v, h, l);
        xh2[(size_t)t * HH + i] = h; xl2[(size_t)t * HH + i] = l;
    }
}

// ---------------- RoPE ----------------
__global__ void k_rope(const int* __restrict__ pos, const float* __restrict__ qkv) {
    int t = blockIdx.x;
    float fp = (float)pos[t];
    for (int idx = threadIdx.x; idx < (NH + NKV) * 64; idx += 256) {
        int hh = idx >> 6, d = idx & 63;
        float inv = powf(1e6f, -(float)d / 64.f);
        float ang = fp * inv;
        float c = cosf(ang), s = sinf(ang);
        const float* p = qkv + (size_t)t * QKVD + hh * HD;
        float x1 = p[d], x2 = p[d + 64];
        float v1 = x1 * c - x2 * s;
        float v2 = x2 * c + x1 * s;
        bf16 h1, l1, h2, l2;
        split_bf(v1, h1, l1); split_bf(v2, h2, l2);
        if (hh < NH) {
            size_t b = (size_t)t * (NH * HD) + hh * HD;
            g_qh[b + d] = h1; g_ql[b + d] = l1;
            g_qh[b + d + 64] = h2; g_ql[b + d + 64] = l2;
        } else {
            int kv = hh - NH;
            size_t b = (size_t)kv * TT * HD + (size_t)t * HD;
            g_kbh[b + d] = h1; g_kbl[b + d] = l1;
            g_kbh[b + d + 64] = h2; g_kbl[b + d + 64] = l2;
        }
    }
}

// ---------------- MoE gating ----------------
__global__ void k_gate(const float* __restrict__ x2, const float* __restrict__ gw,
                       const float* __restrict__ gb,
                       int* __restrict__ ids, float* __restrict__ ws) {
    int t = blockIdx.x;
    int tid = threadIdx.x, wid = tid >> 5, lane = tid & 31;
    __shared__ float logit[NE];
    for (int e = wid; e < NE; e += 8) {
        float acc = 0.f;
        for (int i = lane; i < HH; i += 32)
            acc += x2[(size_t)t * HH + i] * gw[(size_t)e * HH + i];
#pragma unroll
        for (int o = 16; o > 0; o >>= 1) acc += __shfl_down_sync(0xffffffffu, acc, o);
        if (lane == 0) logit[e] = acc;
    }
    __syncthreads();
    if (tid == 0) {
        float s[NE], sc[NE];
        for (int e = 0; e < NE; e++) { s[e] = 1.f / (1.f + expf(-logit[e])); sc[e] = s[e] + gb[e]; }
        float gscore[NGRP];
        for (int g = 0; g < NGRP; g++) {
            float a = -3.4e38f, b = -3.4e38f;
            for (int j = 0; j < GSZ; j++) {
                float v = sc[g * GSZ + j];
                if (v > a) { b = a; a = v; } else if (v > b) b = v;
            }
            gscore[g] = a + b;
        }
        bool gsel[NGRP] = {false, false, false, false};
        for (int k = 0; k < TGRP; k++) {
            int best = -1; float bv = -3.4e38f;
            for (int g = 0; g < NGRP; g++)
                if (!gsel[g] && gscore[g] > bv) { bv = gscore[g]; best = g; }
            gsel[best] = true;
        }
        bool used[NE];
        for (int e = 0; e < NE; e++) used[e] = !gsel[e / GSZ];
        float tsum = 0.f;
        int pick[TOPK]; float pw[TOPK];
        for (int k = 0; k < TOPK; k++) {
            int best = -1; float bv = -3.4e38f;
            for (int e = 0; e < NE; e++)
                if (!used[e] && sc[e] > bv) { bv = sc[e]; best = e; }
            used[best] = true;
            pick[k] = best; pw[k] = s[best]; tsum += s[best];
        }
        float inv = 1.f / tsum;
        for (int k = 0; k < TOPK; k++) {
            ids[t * TOPK + k] = pick[k];
            ws[t * TOPK + k] = pw[k] * inv;
        }
    }
}

__global__ void k_scatter(const int* __restrict__ ids, const float* __restrict__ ws) {
    int i = blockIdx.x * 256 + threadIdx.x;
    if (i >= TT * TOPK) return;
    int e = ids[i];
    int slot = atomicAdd(&g_cnt[e], 1);
    g_tok[e * TT + slot] = i / TOPK;
    g_wgt[e * TT + slot] = ws[i];
}

// ---------------- launch ----------------
extern "C" void kernel_launch(void* const* d_in, const int* in_sizes, int n_in,
                              void* d_out_, int out_size) {
    const int*   positions = (const int*)d_in[0];
    const float* hs   = (const float*)d_in[1];
    const float* res  = (const float*)d_in[2];
    const float* wln1 = (const float*)d_in[3];
    const float* wln2 = (const float*)d_in[4];
    const float* wqkv = (const float*)d_in[5];
    const float* wo   = (const float*)d_in[6];
    const float* gw   = (const float*)d_in[7];
    const float* gb   = (const float*)d_in[8];
    const float* wgu  = (const float*)d_in[9];
    const float* wd   = (const float*)d_in[10];
    float* out  = (float*)d_out_;
    float* res2 = out + (size_t)TT * HH;

    void* p;
    float *res1, *qkv, *x2, *wgt;
    bf16 *xh, *xl, *x2h, *x2l, *ath, *atl, *acth, *vth, *vtl;
    bf16 *wqkvh, *wqkvl, *woh, *wol, *wguh, *wdh;
    int *cnt, *tok, *tkid; float* tkw;
    cudaGetSymbolAddress(&p, g_res1);   res1 = (float*)p;
    cudaGetSymbolAddress(&p, g_qkv);    qkv = (float*)p;
    cudaGetSymbolAddress(&p, g_x2);     x2 = (float*)p;
    cudaGetSymbolAddress(&p, g_xh);  xh = (bf16*)p;  cudaGetSymbolAddress(&p, g_xl);  xl = (bf16*)p;
    cudaGetSymbolAddress(&p, g_x2h); x2h = (bf16*)p; cudaGetSymbolAddress(&p, g_x2l); x2l = (bf16*)p;
    cudaGetSymbolAddress(&p, g_attnh); ath = (bf16*)p; cudaGetSymbolAddress(&p, g_attnl); atl = (bf16*)p;
    cudaGetSymbolAddress(&p, g_acth); acth = (bf16*)p;
    cudaGetSymbolAddress(&p, g_vth); vth = (bf16*)p; cudaGetSymbolAddress(&p, g_vtl); vtl = (bf16*)p;
    cudaGetSymbolAddress(&p, g_wqkvh); wqkvh = (bf16*)p; cudaGetSymbolAddress(&p, g_wqkvl); wqkvl = (bf16*)p;
    cudaGetSymbolAddress(&p, g_woh);   woh = (bf16*)p;   cudaGetSymbolAddress(&p, g_wol);   wol = (bf16*)p;
    cudaGetSymbolAddress(&p, g_wguh);  wguh = (bf16*)p;
    cudaGetSymbolAddress(&p, g_wdh);   wdh = (bf16*)p;
    cudaGetSymbolAddress(&p, g_cnt); cnt = (int*)p;
    cudaGetSymbolAddress(&p, g_tok); tok = (int*)p;
    cudaGetSymbolAddress(&p, g_wgt); wgt = (float*)p;
    cudaGetSymbolAddress(&p, g_topk_id); tkid = (int*)p;
    cudaGetSymbolAddress(&p, g_topk_w);  tkw = (float*)p;

    cudaFuncSetAttribute(gemm_m<false, 6, 3>, cudaFuncAttributeMaxDynamicSharedMemorySize, GSM);
    cudaFuncSetAttribute(gemm_m<false, 2, 3>, cudaFuncAttributeMaxDynamicSharedMemorySize, GSM);
    cudaFuncSetAttribute(gemm_m<true,  5, 2>, cudaFuncAttributeMaxDynamicSharedMemorySize, GSM);
    cudaFuncSetAttribute(gemm_m<false, 7, 1>, cudaFuncAttributeMaxDynamicSharedMemorySize, GSM);
    cudaFuncSetAttribute(k_flash, cudaFuncAttributeMaxDynamicSharedMemorySize, FA_SMEM);

    cudaStream_t s2;
    cudaStreamCreateWithFlags(&s2, cudaStreamNonBlocking);
    cudaEvent_t evFork, evWo, evWgu, evWd;
    cudaEventCreateWithFlags(&evFork, cudaEventDisableTiming);
    cudaEventCreateWithFlags(&evWo,   cudaEventDisableTiming);
    cudaEventCreateWithFlags(&evWgu,  cudaEventDisableTiming);
    cudaEventCreateWithFlags(&evWd,   cudaEventDisableTiming);

    cudaMemsetAsync(qkv, 0, (size_t)TT * QKVD * sizeof(float));
    cudaMemsetAsync(out, 0, (size_t)TT * HH * sizeof(float));
    cudaMemsetAsync(cnt, 0, NE * sizeof(int));

    cudaEventRecord(evFork, 0);
    cudaStreamWaitEvent(s2, evFork, 0);
    { long n = (long)HH * HH;   k_conv<<<(unsigned)((n / 8 + 255) / 256), 256, 0, s2>>>(wo, woh, wol, n); }
    cudaEventRecord(evWo, s2);
    { long n = (long)NE * HH * (IM / 8); k_conv_guh<<<(unsigned)((n + 255) / 256), 256, 0, s2>>>(wgu, wguh); }
    cudaEventRecord(evWgu, s2);
    { long n = (long)NE * IM * HH; k_convh<<<(unsigned)((n / 8 + 255) / 256), 256, 0, s2>>>(wd, wdh, n); }
    cudaEventRecord(evWd, s2);

    // main stream
    { long n = (long)HH * QKVD; k_conv<<<(unsigned)((n / 8 + 255) / 256), 256>>>(wqkv, wqkvh, wqkvl, n); }
    k_addnorm<<<TT, 256>>>(hs, res, wln1, res1);

    // qkv = x @ wqkv  (split-K=3, atomicAdd epilogue, bf16x3)
    { dim3 g(QKVD / BNT, TT / BMT, 3);
      gemm_m<false, 6, 3><<<g, 256, GSM>>>(
          xh, xl, HH, 0, wqkvh, wqkvl, QKVD, 0, 1,
          qkv, nullptr, QKVD, 0, TT, QKVD, HH,
          nullptr, nullptr, 0, nullptr, 0, 1.f); }

    // rope ; V transpose+convert
    k_rope<<<TT, 256>>>(positions, qkv);
    { dim3 g(HD / 32, TT / 32, NKV);
      k_tconv<<<g, dim3(32, 8)>>>(qkv + (NH + NKV) * HD, QKVD, HD, vth, vtl, TT, (long)HD * TT, TT, HD); }

    // flash attention
    { dim3 g(NH, TT / 128); k_flash<<<g, 256, FA_SMEM>>>(); }

    // res2 = attn @ wo + res1 (bf16x3)
    cudaStreamWaitEvent(0, evWo, 0);
    { dim3 g(HH / BNT, TT / BMT, 1);
      gemm_m<false, 2, 3><<<g, 256, GSM>>>(
          ath, atl, HH, 0, woh, wol, HH, 0, 1,
          res2, nullptr, HH, 0, TT, HH, HH,
          nullptr, nullptr, 0, res1, 0, 1.f); }

    // x2 = rmsnorm(res2) -> fp32 + fp16 hi/lo
    k_norm<<<TT, 256>>>(res2, wln2);

    // gating + scatter (pure fp32 inputs — decisions unchanged)
    k_gate<<<TT, 256>>>(x2, gw, gb, tkid, tkw);
    k_scatter<<<(TT * TOPK + 255) / 256, 256>>>(tkid, tkw);

    // per-expert gate_up + fused silu (fp16 2-term; act stored single fp16)
    cudaStreamWaitEvent(0, evWgu, 0);
    { dim3 g((2 * IM) / BNT, TT / BMT, NE);
      gemm_m<true, 5, 2><<<g, 256, GSM>>>(
          x2h, x2l, HH, 0, wguh, nullptr, 2 * IM, (long)HH * 2 * IM, 1,
          nullptr, acth, IM, (long)TT * IM, TT, 2 * IM, HH,
          cnt, tok, TT, nullptr, 0, 1.f); }

    // per-expert down + weighted scatter-add (split-K=2, fp16 single x single)
    cudaStreamWaitEvent(0, evWd, 0);
    { dim3 g(HH / BNT, TT / BMT, NE * 2);
      gemm_m<false, 7, 1><<<g, 256, GSM>>>(
          acth, nullptr, IM, (long)TT * IM, wdh, nullptr, HH, (long)IM * HH, 1,
          out, nullptr, HH, 0, TT, HH, IM,
          cnt, tok, TT, wgt, TT, 1.f); }

    cudaEventDestroy(evFork);
    cudaEventDestroy(evWo);
    cudaEventDestroy(evWgu);
    cudaEventDestroy(evWd);
    cudaStreamDestroy(s2);
}

// round 16
// speedup vs baseline: 1.4327x; 1.1206x over previous
#include <cuda_runtime.h>
#include <cuda_bf16.h>
#include <cuda_fp16.h>
#include <math.h>
#include <stdint.h>

#define TT 2048
#define HH 2048
#define NH 16
#define NKV 4
#define HD 128
#define NE 16
#define TOPK 4
#define NGRP 4
#define GSZ 4
#define TGRP 2
#define IM 1024
#define QKVD 3072
#define ATT_SCALE 0.08838834764831845f
#define EPSV 1e-6f

typedef __nv_bfloat16 bf16;

// ---------------- scratch (device globals; no allocations) ----------------
__device__ float g_res1[(size_t)TT * HH];
__device__ float g_qkv[(size_t)TT * QKVD];
__device__ float g_x2[(size_t)TT * HH];
__device__ bf16  g_xh[(size_t)TT * HH],  g_xl[(size_t)TT * HH];
__device__ bf16  g_x2h[(size_t)TT * HH];                              // fp16 bits (single)
__device__ bf16  g_qh[(size_t)TT * (NH * HD)], g_ql[(size_t)TT * (NH * HD)];
__device__ bf16  g_attnh[(size_t)TT * HH], g_attnl[(size_t)TT * HH];
__device__ bf16  g_acth[(size_t)NE * TT * IM];                        // fp16 bits (single)
__device__ bf16  g_kbh[(size_t)NKV * TT * HD], g_kbl[(size_t)NKV * TT * HD];
__device__ bf16  g_vth[(size_t)NKV * HD * TT], g_vtl[(size_t)NKV * HD * TT];
__device__ bf16  g_wqkvh[(size_t)HH * QKVD], g_wqkvl[(size_t)HH * QKVD];
__device__ bf16  g_woh[(size_t)HH * HH],     g_wol[(size_t)HH * HH];
__device__ bf16  g_wguh[(size_t)NE * HH * 2 * IM];                    // fp16 bits (single)
__device__ bf16  g_wdh[(size_t)NE * IM * HH];                         // fp16 bits (single)
__device__ int   g_cnt[NE];
__device__ int   g_tok[NE * TT];
__device__ float g_wgt[NE * TT];
__device__ int   g_topk_id[TT * TOPK];
__device__ float g_topk_w[TT * TOPK];

// ---------------- helpers ----------------
__device__ __forceinline__ uint32_t smem_u32(const void* p) {
    uint32_t a;
    asm("{ .reg .u64 t; cvta.to.shared.u64 t, %1; cvt.u32.u64 %0, t; }" : "=r"(a) : "l"(p));
    return a;
}
__device__ __forceinline__ void split_bf(float v, bf16& h, bf16& l) {
    h = __float2bfloat16_rn(v);
    l = __float2bfloat16_rn(v - __bfloat162float(h));
}
__device__ __forceinline__ uint32_t pack2(bf16 a, bf16 b) {
    return (uint32_t)__bfloat16_as_ushort(a) | ((uint32_t)__bfloat16_as_ushort(b) << 16);
}
__device__ __forceinline__ uint32_t pack2h(__half a, __half b) {
    return (uint32_t)__half_as_ushort(a) | ((uint32_t)__half_as_ushort(b) << 16);
}
__device__ __forceinline__ void cpa(uint32_t d, const void* s, int sz) {
    asm volatile("cp.async.cg.shared.global [%0], [%1], 16, %2;" :: "r"(d), "l"(s), "r"(sz));
}
__device__ __forceinline__ void cpcommit() { asm volatile("cp.async.commit_group;" ::: "memory"); }
__device__ __forceinline__ void cpwaitN(int n) {
    if (n == 0)      asm volatile("cp.async.wait_group 0;" ::: "memory");
    else if (n == 1) asm volatile("cp.async.wait_group 1;" ::: "memory");
    else             asm volatile("cp.async.wait_group 2;" ::: "memory");
}
__device__ __forceinline__ void ldm4(uint32_t* r, uint32_t a) {
    asm volatile("ldmatrix.sync.aligned.m8n8.x4.shared.b16 {%0,%1,%2,%3}, [%4];"
                 : "=r"(r[0]), "=r"(r[1]), "=r"(r[2]), "=r"(r[3]) : "r"(a));
}
__device__ __forceinline__ void ldm4t(uint32_t* r, uint32_t a) {
    asm volatile("ldmatrix.sync.aligned.m8n8.x4.trans.shared.b16 {%0,%1,%2,%3}, [%4];"
                 : "=r"(r[0]), "=r"(r[1]), "=r"(r[2]), "=r"(r[3]) : "r"(a));
}
// non-volatile — lets ptxas schedule MMAs for ILP.
__device__ __forceinline__ void mma16816(float* c, const uint32_t* a, const uint32_t* b) {
    asm("mma.sync.aligned.m16n8k16.row.col.f32.bf16.bf16.f32 "
        "{%0,%1,%2,%3},{%4,%5,%6,%7},{%8,%9},{%0,%1,%2,%3};"
        : "+f"(c[0]), "+f"(c[1]), "+f"(c[2]), "+f"(c[3])
        : "r"(a[0]), "r"(a[1]), "r"(a[2]), "r"(a[3]), "r"(b[0]), "r"(b[1]));
}
__device__ __forceinline__ void mma16816h(float* c, const uint32_t* a, const uint32_t* b) {
    asm("mma.sync.aligned.m16n8k16.row.col.f32.f16.f16.f32 "
        "{%0,%1,%2,%3},{%4,%5,%6,%7},{%8,%9},{%0,%1,%2,%3};"
        : "+f"(c[0]), "+f"(c[1]), "+f"(c[2]), "+f"(c[3])
        : "r"(a[0]), "r"(a[1]), "r"(a[2]), "r"(a[3]), "r"(b[0]), "r"(b[1]));
}

// ---------------- mma.sync GEMM (B K-major, 3-stage, ILP-ordered MMAs) ------------
// TERMS: 3 = bf16x3 (A hi/lo x B hi/lo), 2 = fp16 A hi/lo x single fp16 B,
//        1 = single fp16 A x single fp16 B (MoE — downstream of all decisions).
// EPI: 0 fp32 store, 2 add X, 3 atomicAdd scatter, 5 silu(even)*odd -> fp16 single,
//      6 split-K (z = slice, batch 0), 7 split-K x2 + scatter (z = expert*2+slice).
#define BMT 128
#define BNT 128
#define BKT 32
#define AST 80u
#define BST 272u
#define A_SZ 10240u
#define B_SZ 8704u
#define STG2 (2u * A_SZ + 2u * B_SZ)   // 37888
#define NSTG 3
#define GSM (NSTG * 37888)             // 113664

template <bool GA, int EPI, int TERMS>
__global__ void __launch_bounds__(256, 2)
gemm_m(const bf16* __restrict__ Ah0, const bf16* __restrict__ Al0, int lda, long saz,
       const bf16* __restrict__ Bh0, const bf16* __restrict__ Bl0, int ldb, long sbz, int bdiv,
       float* __restrict__ C0, bf16* __restrict__ Oh0, int ldc, long scz,
       int M0, int N, int K,
       const int* __restrict__ Mptr, const int* __restrict__ gidx0, int sgz,
       const float* __restrict__ X0, long sxz, float alpha) {
    int z = blockIdx.z;
    int zb = z, ksl = 0, kns = 1;
    if (EPI == 6) { zb = 0; ksl = z; kns = (int)gridDim.z; }
    if (EPI == 7) { zb = z >> 1; ksl = z & 1; kns = 2; }
    int M = Mptr ? Mptr[zb] : M0;
    int row0 = blockIdx.y * BMT, col0 = blockIdx.x * BNT;
    if (row0 >= M) return;

    extern __shared__ char smem[];
    uint32_t sb = smem_u32(smem);
    int tid = threadIdx.x, lane = tid & 31, wid = tid >> 5;
    const int m0w = (wid & 3) * 32, n0w = (wid >> 2) * 64;

    const int* gidxz = (GA || EPI == 3 || EPI == 7) ? gidx0 + (long)zb * sgz : nullptr;
    const float* X = (EPI == 2 || EPI == 3 || EPI == 7) ? X0 + (long)zb * sxz : nullptr;
    const bf16* Bh = Bh0 + (long)(zb / bdiv) * sbz + col0;
    const bf16* Bl = (TERMS == 3) ? (Bl0 + (long)(zb / bdiv) * sbz + col0) : nullptr;

    int nchTot = K / BKT;
    int c0 = (nchTot * ksl) / kns;
    int c1 = (nchTot * (ksl + 1)) / kns;

    int lrow = tid >> 1, lhalf = tid & 1;
    int ari = row0 + lrow;
    bool av = ari < M;
    long agrow = ari;
    if (GA) agrow = av ? (long)gidxz[ari] : 0;
    long arow2 = (GA ? agrow : (long)ari);
    const bf16* agh2 = Ah0 + (long)zb * saz + arow2 * (long)lda;
    const bf16* agl2 = (TERMS >= 2) ? (Al0 + (long)zb * saz + arow2 * (long)lda) : nullptr;
    int asz = av ? 16 : 0;
    uint32_t dst_a = sb + lrow * AST + lhalf * 32;
    int brow = tid >> 3, bth = tid & 7;
    uint32_t dst_b = sb + 2 * A_SZ + brow * BST + bth * 32;

    auto cp_stage = [&](int buf, int k0) {
        uint32_t so = buf * STG2;
        long ko = k0 + lhalf * 16;
        cpa(dst_a + so,             agh2 + ko,     asz);
        cpa(dst_a + so + 16,        agh2 + ko + 8, asz);
        if (TERMS >= 2) {
            cpa(dst_a + so + A_SZ,      agl2 + ko,     asz);
            cpa(dst_a + so + A_SZ + 16, agl2 + ko + 8, asz);
        }
        long bko = (long)(k0 + brow) * ldb + bth * 16;
        cpa(dst_b + so,             Bh + bko,     16);
        cpa(dst_b + so + 16,        Bh + bko + 8, 16);
        if (TERMS == 3) {
            cpa(dst_b + so + B_SZ,      Bl + bko,     16);
            cpa(dst_b + so + B_SZ + 16, Bl + bko + 8, 16);
        }
    };

    float acc[2][8][4];
#pragma unroll
    for (int i = 0; i < 2; i++)
#pragma unroll
        for (int j = 0; j < 8; j++)
#pragma unroll
            for (int q = 0; q < 4; q++) acc[i][j][q] = 0.f;

    uint32_t a_off = (uint32_t)(m0w + (lane & 15)) * AST + (uint32_t)(lane >> 4) * 16;
    uint32_t b_off = (uint32_t)((lane & 7) + ((lane >> 3) & 1) * 8) * BST
                   + (uint32_t)(lane >> 4) * 16;

    auto compute = [&](int buf) {
        uint32_t ab  = sb + buf * STG2;
        uint32_t alb = ab + A_SZ;
        uint32_t bhb = ab + 2 * A_SZ;
        uint32_t blb = bhb + B_SZ;
#pragma unroll
        for (int s = 0; s < 2; s++) {
            uint32_t ka = s * 32;
            uint32_t ah0[4], ah1[4], al0[4], al1[4];
            ldm4(ah0, ab + a_off + ka);
            ldm4(ah1, ab + a_off + 16 * AST + ka);
            if (TERMS >= 2) {
                ldm4(al0, alb + a_off + ka);
                ldm4(al1, alb + a_off + 16 * AST + ka);
            }
            uint32_t bs = b_off + s * (16 * BST);
#pragma unroll
            for (int np = 0; np < 4; np++) {
                uint32_t bo = bs + (uint32_t)((n0w + np * 16) * 2);
                int ne = 2 * np, no = 2 * np + 1;
                if (TERMS == 1) {
                    uint32_t bh[4];
                    ldm4t(bh, bhb + bo);
                    mma16816h(acc[0][ne], ah0, bh);  mma16816h(acc[0][no], ah0, bh + 2);
                    mma16816h(acc[1][ne], ah1, bh);  mma16816h(acc[1][no], ah1, bh + 2);
                } else if (TERMS == 2) {
                    uint32_t bh[4];
                    ldm4t(bh, bhb + bo);
                    mma16816h(acc[0][ne], ah0, bh);  mma16816h(acc[0][no], ah0, bh + 2);
                    mma16816h(acc[1][ne], ah1, bh);  mma16816h(acc[1][no], ah1, bh + 2);
                    mma16816h(acc[0][ne], al0, bh);  mma16816h(acc[0][no], al0, bh + 2);
                    mma16816h(acc[1][ne], al1, bh);  mma16816h(acc[1][no], al1, bh + 2);
                } else {
                    uint32_t bh[4], bl[4];
                    ldm4t(bh, bhb + bo);
                    ldm4t(bl, blb + bo);
                    mma16816(acc[0][ne], ah0, bh);     mma16816(acc[0][no], ah0, bh + 2);
                    mma16816(acc[1][ne], ah1, bh);     mma16816(acc[1][no], ah1, bh + 2);
                    mma16816(acc[0][ne], ah0, bl);     mma16816(acc[0][no], ah0, bl + 2);
                    mma16816(acc[1][ne], ah1, bl);     mma16816(acc[1][no], ah1, bl + 2);
                    mma16816(acc[0][ne], al0, bh);     mma16816(acc[0][no], al0, bh + 2);
                    mma16816(acc[1][ne], al1, bh);     mma16816(acc[1][no], al1, bh + 2);
                }
            }
        }
    };

    cp_stage(0, c0 * BKT); cpcommit();
    cp_stage(1, (c0 + 1) * BKT); cpcommit();
    int buf = 0;
    for (int c = c0; c < c1; c++) {
        cpwaitN(1);
        __syncthreads();
        compute(buf);
        int nb = buf + 1; if (nb == NSTG) nb = 0;
        int pb = buf + 2; if (pb >= NSTG) pb -= NSTG;
        if (c + 2 < c1) cp_stage(pb, (c + 2) * BKT);
        cpcommit();
        buf = nb;
    }

    // epilogue
    int lq = lane >> 2, lr = lane & 3;
#pragma unroll
    for (int mt = 0; mt < 2; mt++) {
        int r0 = row0 + m0w + mt * 16 + lq;
        int r1 = r0 + 8;
#pragma unroll
        for (int nt = 0; nt < 8; nt++) {
            long cc = (long)col0 + n0w + nt * 8 + 2 * lr;
            float v0 = acc[mt][nt][0] * alpha, v1 = acc[mt][nt][1] * alpha;
            float v2 = acc[mt][nt][2] * alpha, v3 = acc[mt][nt][3] * alpha;
            if (EPI == 6) {
                float* C = C0;
                if (r0 < M) {
                    atomicAdd(&C[(long)r0 * ldc + cc], v0);
                    atomicAdd(&C[(long)r0 * ldc + cc + 1], v1);
                }
                if (r1 < M) {
                    atomicAdd(&C[(long)r1 * ldc + cc], v2);
                    atomicAdd(&C[(long)r1 * ldc + cc + 1], v3);
                }
            } else if (EPI == 3 || EPI == 7) {
                float* C = C0 + (EPI == 3 ? (long)zb * scz : 0);
                if (r0 < M) {
                    long gr = gidxz[r0]; float w = X[r0];
                    atomicAdd(&C[gr * ldc + cc], w * v0);
                    atomicAdd(&C[gr * ldc + cc + 1], w * v1);
                }
                if (r1 < M) {
                    long gr = gidxz[r1]; float w = X[r1];
                    atomicAdd(&C[gr * ldc + cc], w * v2);
                    atomicAdd(&C[gr * ldc + cc + 1], w * v3);
                }
            } else if (EPI == 5) {
                __half* oh = (__half*)(Oh0 + (long)zb * scz);
                long co = cc >> 1;
                if (r0 < M) {
                    float a = v0 / (1.f + expf(-v0)) * v1;
                    oh[(long)r0 * ldc + co] = __float2half_rn(a);
                }
                if (r1 < M) {
                    float a = v2 / (1.f + expf(-v2)) * v3;
                    oh[(long)r1 * ldc + co] = __float2half_rn(a);
                }
            } else if (EPI == 2) {
                float* C = C0 + (long)zb * scz;
                if (r0 < M) {
                    float2 xv = *(const float2*)&X[(long)r0 * ldc + cc];
                    *(float2*)&C[(long)r0 * ldc + cc] = make_float2(v0 + xv.x, v1 + xv.y);
                }
                if (r1 < M) {
                    float2 xv = *(const float2*)&X[(long)r1 * ldc + cc];
                    *(float2*)&C[(long)r1 * ldc + cc] = make_float2(v2 + xv.x, v3 + xv.y);
                }
            } else {
                float* C = C0 + (long)zb * scz;
                if (r0 < M) *(float2*)&C[(long)r0 * ldc + cc] = make_float2(v0, v1);
                if (r1 < M) *(float2*)&C[(long)r1 * ldc + cc] = make_float2(v2, v3);
            }
        }
    }
}

// ---------------- flash attention (bf16x3, online softmax) ----------------
#define FA_Q  0u
#define FA_QL 40960u
#define FA_K  81920u
#define FA_KL 122880u
#define FA_V  163840u
#define FA_VL 184320u
#define FA_SMEM 204800

__global__ void __launch_bounds__(256, 1) k_flash() {
    extern __shared__ char smem[];
    uint32_t sb = smem_u32(smem);
    int head = blockIdx.x;
    int qb = (int)gridDim.y - 1 - (int)blockIdx.y;
    int row0 = qb * 128;
    int kv = head >> 2;
    int tid = threadIdx.x, lane = tid & 31, w = tid >> 5;
    int lq = lane >> 2, lr = lane & 3;
    int lrow = tid >> 1, lhalf = tid & 1;

    const bf16* qgh = g_qh + (size_t)(row0 + lrow) * (NH * HD) + head * HD + lhalf * 16;
    const bf16* qgl = g_ql + (size_t)(row0 + lrow) * (NH * HD) + head * HD + lhalf * 16;
    const bf16* kgh = g_kbh + (size_t)kv * TT * HD + (size_t)lrow * HD + lhalf * 16;
    const bf16* kgl = g_kbl + (size_t)kv * TT * HD + (size_t)lrow * HD + lhalf * 16;
    const bf16* vgh = g_vth + (size_t)kv * HD * TT + (size_t)lrow * TT + lhalf * 16;
    const bf16* vgl = g_vtl + (size_t)kv * HD * TT + (size_t)lrow * TT + lhalf * 16;

#pragma unroll
    for (int c = 0; c < 4; c++) {
        uint32_t d = sb + FA_Q + (uint32_t)((c * 128 + lrow) * 80) + lhalf * 32;
        cpa(d, qgh + c * 32, 16); cpa(d + 16, qgh + c * 32 + 8, 16);
        uint32_t dl = d + (FA_QL - FA_Q);
        cpa(dl, qgl + c * 32, 16); cpa(dl + 16, qgl + c * 32 + 8, 16);
    }
    cpcommit();

    auto issueK = [&](int s0) {
#pragma unroll
        for (int c = 0; c < 4; c++) {
            uint32_t d = sb + FA_K + (uint32_t)((c * 128 + lrow) * 80) + lhalf * 32;
            const bf16* s = kgh + (size_t)s0 * HD + c * 32;
            cpa(d, s, 16); cpa(d + 16, s + 8, 16);
            uint32_t dl = d + (FA_KL - FA_K);
            const bf16* sl = kgl + (size_t)s0 * HD + c * 32;
            cpa(dl, sl, 16); cpa(dl + 16, sl + 8, 16);
        }
        cpcommit();
    };
    auto issueV = [&](int s0, int c) {
        uint32_t d = sb + FA_V + (uint32_t)(((c & 1) * 128 + lrow) * 80) + lhalf * 32;
        const bf16* s = vgh + s0 + c * 32;
        cpa(d, s, 16); cpa(d + 16, s + 8, 16);
        uint32_t dl = d + (FA_VL - FA_V);
        const bf16* sl = vgl + s0 + c * 32;
        cpa(dl, sl, 16); cpa(dl + 16, sl + 8, 16);
        cpcommit();
    };
    issueK(0);

    float O[16][4];
#pragma unroll
    for (int i = 0; i < 16; i++) { O[i][0] = O[i][1] = O[i][2] = O[i][3] = 0.f; }
    float m_lo = -1e30f, m_hi = -1e30f, l_lo = 0.f, l_hi = 0.f;
    int ntl = qb + 1;
    uint32_t a_off = (uint32_t)((w * 16 + (lane & 15)) * 80) + (uint32_t)(lane >> 4) * 16;
    uint32_t b_off = (uint32_t)((((lane >> 4) << 3) + (lane & 7)) * 80) + (uint32_t)((lane >> 3) & 1) * 16;

    for (int st = 0; st < ntl; st++) {
        int s0 = st * 128;
        __syncthreads();
        issueV(s0, 0); issueV(s0, 1);
        asm volatile("cp.async.wait_group 2;" ::: "memory");
        __syncthreads();

        float S[16][4];
#pragma unroll
        for (int i = 0; i < 16; i++) { S[i][0] = S[i][1] = S[i][2] = S[i][3] = 0.f; }
#pragma unroll
        for (int kc = 0; kc < 4; kc++)
#pragma unroll
        for (int ks = 0; ks < 2; ks++) {
            uint32_t qa = sb + (uint32_t)(kc * 128 * 80) + a_off + ks * 32;
            uint32_t ah[4], al[4];
            ldm4(ah, qa + FA_Q);
            ldm4(al, qa + FA_QL);
#pragma unroll
            for (int j = 0; j < 8; j++) {
                uint32_t kb = sb + FA_K + (uint32_t)((kc * 128 + 16 * j) * 80) + b_off + ks * 32;
                uint32_t bh[4], bl[4];
                ldm4(bh, kb); ldm4(bl, kb + (FA_KL - FA_K));
                mma16816(S[2 * j],     ah, bh);     mma16816(S[2 * j + 1], ah, bh + 2);
                mma16816(S[2 * j],     ah, bl);     mma16816(S[2 * j + 1], ah, bl + 2);
                mma16816(S[2 * j],     al, bh);     mma16816(S[2 * j + 1], al, bh + 2);
            }
        }

        bool dg = (st == qb);
        int rlo = row0 + w * 16 + lq, rhi = rlo + 8;
#pragma unroll
        for (int nt = 0; nt < 16; nt++) {
            int cbase = s0 + nt * 8 + 2 * lr;
#pragma unroll
            for (int q = 0; q < 4; q++) {
                float v = S[nt][q] * ATT_SCALE;
                int col = cbase + (q & 1);
                int rw = (q < 2) ? rlo : rhi;
                if (dg && col > rw) v = -1e30f;
                S[nt][q] = v;
            }
        }
        float mx0 = -1e30f, mx1 = -1e30f;
#pragma unroll
        for (int nt = 0; nt < 16; nt++) {
            mx0 = fmaxf(mx0, fmaxf(S[nt][0], S[nt][1]));
            mx1 = fmaxf(mx1, fmaxf(S[nt][2], S[nt][3]));
        }
        mx0 = fmaxf(mx0, __shfl_xor_sync(0xffffffffu, mx0, 1));
        mx0 = fmaxf(mx0, __shfl_xor_sync(0xffffffffu, mx0, 2));
        mx1 = fmaxf(mx1, __shfl_xor_sync(0xffffffffu, mx1, 1));
        mx1 = fmaxf(mx1, __shfl_xor_sync(0xffffffffu, mx1, 2));
        float mn0 = fmaxf(m_lo, mx0), mn1 = fmaxf(m_hi, mx1);
        float sc0 = expf(m_lo - mn0), sc1 = expf(m_hi - mn1);
        float rs0 = 0.f, rs1 = 0.f;
#pragma unroll
        for (int nt = 0; nt < 16; nt++) {
            S[nt][0] = expf(S[nt][0] - mn0); S[nt][1] = expf(S[nt][1] - mn0);
            S[nt][2] = expf(S[nt][2] - mn1); S[nt][3] = expf(S[nt][3] - mn1);
            rs0 += S[nt][0] + S[nt][1];
            rs1 += S[nt][2] + S[nt][3];
        }
        rs0 += __shfl_xor_sync(0xffffffffu, rs0, 1); rs0 += __shfl_xor_sync(0xffffffffu, rs0, 2);
        rs1 += __shfl_xor_sync(0xffffffffu, rs1, 1); rs1 += __shfl_xor_sync(0xffffffffu, rs1, 2);
        l_lo = l_lo * sc0 + rs0; l_hi = l_hi * sc1 + rs1;
        m_lo = mn0; m_hi = mn1;
#pragma unroll
        for (int nt = 0; nt < 16; nt++) {
            O[nt][0] *= sc0; O[nt][1] *= sc0; O[nt][2] *= sc1; O[nt][3] *= sc1;
        }

        __syncthreads();
        bool haveK = (st + 1 < ntl);
        if (haveK) issueK(s0 + 128);

#pragma unroll 1
        for (int c = 0; c < 4; c++) {
            int pend = haveK ? (c <= 1 ? 2 : (c == 2 ? 1 : 0)) : (c < 3 ? 1 : 0);
            cpwaitN(pend);
            __syncthreads();
#pragma unroll
            for (int ks = 0; ks < 2; ks++) {
                int t0 = 2 * (2 * c + ks), t1 = t0 + 1;
                uint32_t pah[4], pal[4];
                bf16 h0, l0, h1, l1;
                split_bf(S[t0][0], h0, l0); split_bf(S[t0][1], h1, l1);
                pah[0] = pack2(h0, h1); pal[0] = pack2(l0, l1);
                split_bf(S[t0][2], h0, l0); split_bf(S[t0][3], h1, l1);
                pah[1] = pack2(h0, h1); pal[1] = pack2(l0, l1);
                split_bf(S[t1][0], h0, l0); split_bf(S[t1][1], h1, l1);
                pah[2] = pack2(h0, h1); pal[2] = pack2(l0, l1);
                split_bf(S[t1][2], h0, l0); split_bf(S[t1][3], h1, l1);
                pah[3] = pack2(h0, h1); pal[3] = pack2(l0, l1);
#pragma unroll
                for (int j = 0; j < 8; j++) {
                    uint32_t vb = sb + FA_V + (uint32_t)((((c & 1) * 128) + 16 * j) * 80) + b_off + ks * 32;
                    uint32_t vh[4], vl[4];
                    ldm4(vh, vb); ldm4(vl, vb + (FA_VL - FA_V));
                    mma16816(O[2 * j],     pah, vh);     mma16816(O[2 * j + 1], pah, vh + 2);
                    mma16816(O[2 * j],     pah, vl);     mma16816(O[2 * j + 1], pah, vl + 2);
                    mma16816(O[2 * j],     pal, vh);     mma16816(O[2 * j + 1], pal, vh + 2);
                }
            }
            __syncthreads();
            if (c + 2 < 4) issueV(s0, c + 2);
        }
    }

    float il0 = 1.f / l_lo, il1 = 1.f / l_hi;
    int rlo = row0 + w * 16 + lq, rhi = rlo + 8;
#pragma unroll
    for (int nt = 0; nt < 16; nt++) {
        long col = (long)head * HD + nt * 8 + 2 * lr;
        bf16 h0, l0, h1, l1;
        float v0 = O[nt][0] * il0, v1 = O[nt][1] * il0;
        split_bf(v0, h0, l0); split_bf(v1, h1, l1);
        *(uint32_t*)&g_attnh[(long)rlo * HH + col] = pack2(h0, h1);
        *(uint32_t*)&g_attnl[(long)rlo * HH + col] = pack2(l0, l1);
        float v2 = O[nt][2] * il1, v3 = O[nt][3] * il1;
        split_bf(v2, h0, l0); split_bf(v3, h1, l1);
        *(uint32_t*)&g_attnh[(long)rhi * HH + col] = pack2(h0, h1);
        *(uint32_t*)&g_attnl[(long)rhi * HH + col] = pack2(l0, l1);
    }
}

// ---------------- streaming convert fp32 -> bf16 hi/lo (8 elems/thread) -----------
__global__ void k_conv(const float* __restrict__ in, bf16* __restrict__ oh,
                       bf16* __restrict__ ol, long n) {
    long i = ((long)blockIdx.x * 256 + threadIdx.x) * 8;
    if (i >= n) return;
    float4 a = *(const float4*)(in + i);
    float4 b = *(const float4*)(in + i + 4);
    bf16 h0, l0, h1, l1;
    uint32_t H[4], L[4];
    split_bf(a.x, h0, l0); split_bf(a.y, h1, l1); H[0] = pack2(h0, h1); L[0] = pack2(l0, l1);
    split_bf(a.z, h0, l0); split_bf(a.w, h1, l1); H[1] = pack2(h0, h1); L[1] = pack2(l0, l1);
    split_bf(b.x, h0, l0); split_bf(b.y, h1, l1); H[2] = pack2(h0, h1); L[2] = pack2(l0, l1);
    split_bf(b.z, h0, l0); split_bf(b.w, h1, l1); H[3] = pack2(h0, h1); L[3] = pack2(l0, l1);
    *(uint4*)(oh + i) = make_uint4(H[0], H[1], H[2], H[3]);
    *(uint4*)(ol + i) = make_uint4(L[0], L[1], L[2], L[3]);
}

// fp32 -> single fp16 (8 elems/thread) for wd
__global__ void k_convh(const float* __restrict__ in, bf16* __restrict__ oh, long n) {
    long i = ((long)blockIdx.x * 256 + threadIdx.x) * 8;
    if (i >= n) return;
    float4 a = *(const float4*)(in + i);
    float4 b = *(const float4*)(in + i + 4);
    uint32_t H[4];
    H[0] = pack2h(__float2half_rn(a.x), __float2half_rn(a.y));
    H[1] = pack2h(__float2half_rn(a.z), __float2half_rn(a.w));
    H[2] = pack2h(__float2half_rn(b.x), __float2half_rn(b.y));
    H[3] = pack2h(__float2half_rn(b.z), __float2half_rn(b.w));
    *(uint4*)(oh + i) = make_uint4(H[0], H[1], H[2], H[3]);
}

// gate/up column interleave, single fp16 (8 gate + 8 up per thread)
__global__ void k_conv_guh(const float* __restrict__ in, bf16* __restrict__ oh) {
    long t = (long)blockIdx.x * 256 + threadIdx.x;
    long rows = (long)NE * HH;
    long perRow = IM / 8;
    if (t >= rows * perRow) return;
    long row = t / perRow;
    long c = (t % perRow) * 8;
    const float* base = in + row * (2 * IM);
    float4 gA = *(const float4*)(base + c);
    float4 gB = *(const float4*)(base + c + 4);
    float4 uA = *(const float4*)(base + IM + c);
    float4 uB = *(const float4*)(base + IM + c + 4);
    uint32_t H[8];
    H[0] = pack2h(__float2half_rn(gA.x), __float2half_rn(uA.x));
    H[1] = pack2h(__float2half_rn(gA.y), __float2half_rn(uA.y));
    H[2] = pack2h(__float2half_rn(gA.z), __float2half_rn(uA.z));
    H[3] = pack2h(__float2half_rn(gA.w), __float2half_rn(uA.w));
    H[4] = pack2h(__float2half_rn(gB.x), __float2half_rn(uB.x));
    H[5] = pack2h(__float2half_rn(gB.y), __float2half_rn(uB.y));
    H[6] = pack2h(__float2half_rn(gB.z), __float2half_rn(uB.z));
    H[7] = pack2h(__float2half_rn(gB.w), __float2half_rn(uB.w));
    bf16* po = oh + row * (2 * IM) + 2 * c;
    *(uint4*)po       = make_uint4(H[0], H[1], H[2], H[3]);
    *(uint4*)(po + 8) = make_uint4(H[4], H[5], H[6], H[7]);
}

// ---------------- transpose + convert (V only) ----------------
__global__ void k_tconv(const float* __restrict__ in, long ldin, long sbin,
                        bf16* __restrict__ oh, bf16* __restrict__ ol, long ldo, long sbo,
                        int R, int C) {
    __shared__ float t[32][33];
    int z = blockIdx.z;
    const float* I = in + (long)z * sbin;
    int c0 = blockIdx.x * 32, r0 = blockIdx.y * 32;
#pragma unroll
    for (int i = 0; i < 4; i++) {
        int r = r0 + threadIdx.y + i * 8, c = c0 + threadIdx.x;
        t[threadIdx.y + i * 8][threadIdx.x] = (r < R && c < C) ? I[(long)r * ldin + c] : 0.f;
    }
    __syncthreads();
#pragma unroll
    for (int i = 0; i < 4; i++) {
        int orow = c0 + threadIdx.y + i * 8, ocol = r0 + threadIdx.x;
        if (orow < C && ocol < R) {
            bf16 h, l;
            split_bf(t[threadIdx.x][threadIdx.y + i * 8], h, l);
            oh[(long)z * sbo + (long)orow * ldo + ocol] = h;
            ol[(long)z * sbo + (long)orow * ldo + ocol] = l;
        }
    }
}

// ---------------- residual add + rmsnorm ----------------
__global__ void k_addnorm(const float* __restrict__ hs, const float* __restrict__ res,
                          const float* __restrict__ w, float* __restrict__ res_out) {
    int t = blockIdx.x;
    __shared__ float red[256];
    float ss = 0.f;
    for (int i = threadIdx.x; i < HH; i += 256) {
        float v = hs[(size_t)t * HH + i] + res[(size_t)t * HH + i];
        res_out[(size_t)t * HH + i] = v;
        ss += v * v;
    }
    red[threadIdx.x] = ss; __syncthreads();
    for (int s = 128; s > 0; s >>= 1) { if (threadIdx.x < s) red[threadIdx.x] += red[threadIdx.x + s]; __syncthreads(); }
    float inv = rsqrtf(red[0] / (float)HH + EPSV);
    for (int i = threadIdx.x; i < HH; i += 256) {
        float v = res_out[(size_t)t * HH + i] * inv * w[i];
        bf16 h, l; split_bf(v, h, l);
        g_xh[(size_t)t * HH + i] = h; g_xl[(size_t)t * HH + i] = l;
    }
}

// rmsnorm -> fp32 x2 (gating) + single fp16 (MoE A operand)
__global__ void k_norm(const float* __restrict__ in, const float* __restrict__ w) {
    int t = blockIdx.x;
    __shared__ float red[256];
    float ss = 0.f;
    for (int i = threadIdx.x; i < HH; i += 256) { float v = in[(size_t)t * HH + i]; ss += v * v; }
    red[threadIdx.x] = ss; __syncthreads();
    for (int s = 128; s > 0; s >>= 1) { if (threadIdx.x < s) red[threadIdx.x] += red[threadIdx.x + s]; __syncthreads(); }
    float inv = rsqrtf(red[0] / (float)HH + EPSV);
    __half* xh2 = (__half*)g_x2h;
    for (int i = threadIdx.x; i < HH; i += 256) {
        float v = in[(size_t)t * HH + i] * inv * w[i];
        g_x2[(size_t)t * HH + i] = v;
        xh2[(size_t)t * HH + i] = __float2half_rn(v);
    }
}

// ---------------- RoPE ----------------
__global__ void k_rope(const int* __restrict__ pos, const float* __restrict__ qkv) {
    int t = blockIdx.x;
    float fp = (float)pos[t];
    for (int idx = threadIdx.x; idx < (NH + NKV) * 64; idx += 256) {
        int hh = idx >> 6, d = idx & 63;
        float inv = powf(1e6f, -(float)d / 64.f);
        float ang = fp * inv;
        float c = cosf(ang), s = sinf(ang);
        const float* p = qkv + (size_t)t * QKVD + hh * HD;
        float x1 = p[d], x2 = p[d + 64];
        float v1 = x1 * c - x2 * s;
        float v2 = x2 * c + x1 * s;
        bf16 h1, l1, h2, l2;
        split_bf(v1, h1, l1); split_bf(v2, h2, l2);
        if (hh < NH) {
            size_t b = (size_t)t * (NH * HD) + hh * HD;
            g_qh[b + d] = h1; g_ql[b + d] = l1;
            g_qh[b + d + 64] = h2; g_ql[b + d + 64] = l2;
        } else {
            int kv = hh - NH;
            size_t b = (size_t)kv * TT * HD + (size_t)t * HD;
            g_kbh[b + d] = h1; g_kbl[b + d] = l1;
            g_kbh[b + d + 64] = h2; g_kbl[b + d + 64] = l2;
        }
    }
}

// ---------------- MoE gating ----------------
__global__ void k_gate(const float* __restrict__ x2, const float* __restrict__ gw,
                       const float* __restrict__ gb,
                       int* __restrict__ ids, float* __restrict__ ws) {
    int t = blockIdx.x;
    int tid = threadIdx.x, wid = tid >> 5, lane = tid & 31;
    __shared__ float logit[NE];
    for (int e = wid; e < NE; e += 8) {
        float acc = 0.f;
        for (int i = lane; i < HH; i += 32)
            acc += x2[(size_t)t * HH + i] * gw[(size_t)e * HH + i];
#pragma unroll
        for (int o = 16; o > 0; o >>= 1) acc += __shfl_down_sync(0xffffffffu, acc, o);
        if (lane == 0) logit[e] = acc;
    }
    __syncthreads();
    if (tid == 0) {
        float s[NE], sc[NE];
        for (int e = 0; e < NE; e++) { s[e] = 1.f / (1.f + expf(-logit[e])); sc[e] = s[e] + gb[e]; }
        float gscore[NGRP];
        for (int g = 0; g < NGRP; g++) {
            float a = -3.4e38f, b = -3.4e38f;
            for (int j = 0; j < GSZ; j++) {
                float v = sc[g * GSZ + j];
                if (v > a) { b = a; a = v; } else if (v > b) b = v;
            }
            gscore[g] = a + b;
        }
        bool gsel[NGRP] = {false, false, false, false};
        for (int k = 0; k < TGRP; k++) {
            int best = -1; float bv = -3.4e38f;
            for (int g = 0; g < NGRP; g++)
                if (!gsel[g] && gscore[g] > bv) { bv = gscore[g]; best = g; }
            gsel[best] = true;
        }
        bool used[NE];
        for (int e = 0; e < NE; e++) used[e] = !gsel[e / GSZ];
        float tsum = 0.f;
        int pick[TOPK]; float pw[TOPK];
        for (int k = 0; k < TOPK; k++) {
            int best = -1; float bv = -3.4e38f;
            for (int e = 0; e < NE; e++)
                if (!used[e] && sc[e] > bv) { bv = sc[e]; best = e; }
            used[best] = true;
            pick[k] = best; pw[k] = s[best]; tsum += s[best];
        }
        float inv = 1.f / tsum;
        for (int k = 0; k < TOPK; k++) {
            ids[t * TOPK + k] = pick[k];
            ws[t * TOPK + k] = pw[k] * inv;
        }
    }
}

__global__ void k_scatter(const int* __restrict__ ids, const float* __restrict__ ws) {
    int i = blockIdx.x * 256 + threadIdx.x;
    if (i >= TT * TOPK) return;
    int e = ids[i];
    int slot = atomicAdd(&g_cnt[e], 1);
    g_tok[e * TT + slot] = i / TOPK;
    g_wgt[e * TT + slot] = ws[i];
}

// ---------------- launch ----------------
extern "C" void kernel_launch(void* const* d_in, const int* in_sizes, int n_in,
                              void* d_out_, int out_size) {
    const int*   positions = (const int*)d_in[0];
    const float* hs   = (const float*)d_in[1];
    const float* res  = (const float*)d_in[2];
    const float* wln1 = (const float*)d_in[3];
    const float* wln2 = (const float*)d_in[4];
    const float* wqkv = (const float*)d_in[5];
    const float* wo   = (const float*)d_in[6];
    const float* gw   = (const float*)d_in[7];
    const float* gb   = (const float*)d_in[8];
    const float* wgu  = (const float*)d_in[9];
    const float* wd   = (const float*)d_in[10];
    float* out  = (float*)d_out_;
    float* res2 = out + (size_t)TT * HH;

    void* p;
    float *res1, *qkv, *x2, *wgt;
    bf16 *xh, *xl, *x2h, *ath, *atl, *acth, *vth, *vtl;
    bf16 *wqkvh, *wqkvl, *woh, *wol, *wguh, *wdh;
    int *cnt, *tok, *tkid; float* tkw;
    cudaGetSymbolAddress(&p, g_res1);   res1 = (float*)p;
    cudaGetSymbolAddress(&p, g_qkv);    qkv = (float*)p;
    cudaGetSymbolAddress(&p, g_x2);     x2 = (float*)p;
    cudaGetSymbolAddress(&p, g_xh);  xh = (bf16*)p;  cudaGetSymbolAddress(&p, g_xl);  xl = (bf16*)p;
    cudaGetSymbolAddress(&p, g_x2h); x2h = (bf16*)p;
    cudaGetSymbolAddress(&p, g_attnh); ath = (bf16*)p; cudaGetSymbolAddress(&p, g_attnl); atl = (bf16*)p;
    cudaGetSymbolAddress(&p, g_acth); acth = (bf16*)p;
    cudaGetSymbolAddress(&p, g_vth); vth = (bf16*)p; cudaGetSymbolAddress(&p, g_vtl); vtl = (bf16*)p;
    cudaGetSymbolAddress(&p, g_wqkvh); wqkvh = (bf16*)p; cudaGetSymbolAddress(&p, g_wqkvl); wqkvl = (bf16*)p;
    cudaGetSymbolAddress(&p, g_woh);   woh = (bf16*)p;   cudaGetSymbolAddress(&p, g_wol);   wol = (bf16*)p;
    cudaGetSymbolAddress(&p, g_wguh);  wguh = (bf16*)p;
    cudaGetSymbolAddress(&p, g_wdh);   wdh = (bf16*)p;
    cudaGetSymbolAddress(&p, g_cnt); cnt = (int*)p;
    cudaGetSymbolAddress(&p, g_tok); tok = (int*)p;
    cudaGetSymbolAddress(&p, g_wgt); wgt = (float*)p;
    cudaGetSymbolAddress(&p, g_topk_id); tkid = (int*)p;
    cudaGetSymbolAddress(&p, g_topk_w);  tkw = (float*)p;

    cudaFuncSetAttribute(gemm_m<false, 6, 3>, cudaFuncAttributeMaxDynamicSharedMemorySize, GSM);
    cudaFuncSetAttribute(gemm_m<false, 2, 3>, cudaFuncAttributeMaxDynamicSharedMemorySize, GSM);
    cudaFuncSetAttribute(gemm_m<true,  5, 1>, cudaFuncAttributeMaxDynamicSharedMemorySize, GSM);
    cudaFuncSetAttribute(gemm_m<false, 7, 1>, cudaFuncAttributeMaxDynamicSharedMemorySize, GSM);
    cudaFuncSetAttribute(k_flash, cudaFuncAttributeMaxDynamicSharedMemorySize, FA_SMEM);

    cudaStream_t s2;
    cudaStreamCreateWithFlags(&s2, cudaStreamNonBlocking);
    cudaEvent_t evFork, evWo, evWgu, evWd;
    cudaEventCreateWithFlags(&evFork, cudaEventDisableTiming);
    cudaEventCreateWithFlags(&evWo,   cudaEventDisableTiming);
    cudaEventCreateWithFlags(&evWgu,  cudaEventDisableTiming);
    cudaEventCreateWithFlags(&evWd,   cudaEventDisableTiming);

    cudaMemsetAsync(qkv, 0, (size_t)TT * QKVD * sizeof(float));
    cudaMemsetAsync(out, 0, (size_t)TT * HH * sizeof(float));
    cudaMemsetAsync(cnt, 0, NE * sizeof(int));

    cudaEventRecord(evFork, 0);
    cudaStreamWaitEvent(s2, evFork, 0);
    { long n = (long)HH * HH;   k_conv<<<(unsigned)((n / 8 + 255) / 256), 256, 0, s2>>>(wo, woh, wol, n); }
    cudaEventRecord(evWo, s2);
    { long n = (long)NE * HH * (IM / 8); k_conv_guh<<<(unsigned)((n + 255) / 256), 256, 0, s2>>>(wgu, wguh); }
    cudaEventRecord(evWgu, s2);
    { long n = (long)NE * IM * HH; k_convh<<<(unsigned)((n / 8 + 255) / 256), 256, 0, s2>>>(wd, wdh, n); }
    cudaEventRecord(evWd, s2);

    // main stream
    { long n = (long)HH * QKVD; k_conv<<<(unsigned)((n / 8 + 255) / 256), 256>>>(wqkv, wqkvh, wqkvl, n); }
    k_addnorm<<<TT, 256>>>(hs, res, wln1, res1);

    // qkv = x @ wqkv  (split-K=3, atomicAdd epilogue, bf16x3)
    { dim3 g(QKVD / BNT, TT / BMT, 3);
      gemm_m<false, 6, 3><<<g, 256, GSM>>>(
          xh, xl, HH, 0, wqkvh, wqkvl, QKVD, 0, 1,
          qkv, nullptr, QKVD, 0, TT, QKVD, HH,
          nullptr, nullptr, 0, nullptr, 0, 1.f); }

    // rope ; V transpose+convert
    k_rope<<<TT, 256>>>(positions, qkv);
    { dim3 g(HD / 32, TT / 32, NKV);
      k_tconv<<<g, dim3(32, 8)>>>(qkv + (NH + NKV) * HD, QKVD, HD, vth, vtl, TT, (long)HD * TT, TT, HD); }

    // flash attention
    { dim3 g(NH, TT / 128); k_flash<<<g, 256, FA_SMEM>>>(); }

    // res2 = attn @ wo + res1 (bf16x3)
    cudaStreamWaitEvent(0, evWo, 0);
    { dim3 g(HH / BNT, TT / BMT, 1);
      gemm_m<false, 2, 3><<<g, 256, GSM>>>(
          ath, atl, HH, 0, woh, wol, HH, 0, 1,
          res2, nullptr, HH, 0, TT, HH, HH,
          nullptr, nullptr, 0, res1, 0, 1.f); }

    // x2 = rmsnorm(res2) -> fp32 + single fp16
    k_norm<<<TT, 256>>>(res2, wln2);

    // gating + scatter (pure fp32 inputs — decisions unchanged)
    k_gate<<<TT, 256>>>(x2, gw, gb, tkid, tkw);
    k_scatter<<<(TT * TOPK + 255) / 256, 256>>>(tkid, tkw);

    // per-expert gate_up + fused silu (fp16 single x single; act stored single fp16)
    cudaStreamWaitEvent(0, evWgu, 0);
    { dim3 g((2 * IM) / BNT, TT / BMT, NE);
      gemm_m<true, 5, 1><<<g, 256, GSM>>>(
          x2h, nullptr, HH, 0, wguh, nullptr, 2 * IM, (long)HH * 2 * IM, 1,
          nullptr, acth, IM, (long)TT * IM, TT, 2 * IM, HH,
          cnt, tok, TT, nullptr, 0, 1.f); }

    // per-expert down + weighted scatter-add (split-K=2, fp16 single x single)
    cudaStreamWaitEvent(0, evWd, 0);
    { dim3 g(HH / BNT, TT / BMT, NE * 2);
      gemm_m<false, 7, 1><<<g, 256, GSM>>>(
          acth, nullptr, IM, (long)TT * IM, wdh, nullptr, HH, (long)IM * HH, 1,
          out, nullptr, HH, 0, TT, HH, IM,
          cnt, tok, TT, wgt, TT, 1.f); }

    cudaEventDestroy(evFork);
    cudaEventDestroy(evWo);
    cudaEventDestroy(evWgu);
    cudaEventDestroy(evWd);
    cudaStreamDestroy(s2);
}